// round 8
// baseline (speedup 1.0000x reference)
#include <cuda_runtime.h>
#include <stdint.h>

#define HID   32
#define LEN   32768
#define BATCH 16
#define KLCH  128

#define HSS 136   // hs row stride (floats); 34 float4 granules per row
#define XSS 132   // xs row stride (floats)

// smem float offsets
#define OF_WT1  0                  // 3072 : conv W, fragment order
#define OF_WT2  3072               // 6144 : LVC W, fragment order
#define OF_BIAS 9216               // 64
#define OF_CB   9280               // 32
#define OF_HS   9312               // 32 x 136 = 4352 (single buffer)
#define OF_XS   13664              // 32 x 132 = 4224
#define SMEM_FLOATS 17888          // 71,552 bytes -> 3 CTA/SM (214.7 KB)

// LVC kernel pre-packed in MMA B-fragment order: g_kt[b][l][f], f in [0,6144)
__device__ __align__(16) float g_kt[(size_t)BATCH * KLCH * 6144];
// conv W pre-packed in fragment order (N=32 variant)
__device__ __align__(16) float g_w1f[3072];

__device__ __forceinline__ float tf32r(float x) {
    uint32_t r; asm("cvt.rna.tf32.f32 %0, %1;" : "=r"(r) : "f"(x)); return __uint_as_float(r);
}
__device__ __forceinline__ float fast_tanh(float x) { float r; asm("tanh.approx.f32 %0, %1;" : "=f"(r) : "f"(x)); return r; }
__device__ __forceinline__ float fast_ex2(float x)  { float r; asm("ex2.approx.f32 %0, %1;"  : "=f"(r) : "f"(x)); return r; }
__device__ __forceinline__ float fast_rcp(float x)  { float r; asm("rcp.approx.f32 %0, %1;"  : "=f"(r) : "f"(x)); return r; }

__device__ __forceinline__ uint32_t smem_u32(const void* p) {
    uint32_t a; asm("{ .reg .u64 t; cvta.to.shared.u64 t, %1; cvt.u32.u64 %0, t; }" : "=r"(a) : "l"(p));
    return a;
}
__device__ __forceinline__ void cp_async16(uint32_t dst, const void* src, int src_bytes) {
    asm volatile("cp.async.ca.shared.global [%0], [%1], 16, %2;"
                 :: "r"(dst), "l"(src), "r"(src_bytes) : "memory");
}

__device__ __forceinline__ void mma_tf32(float c[4],
                                         uint32_t a0, uint32_t a1, uint32_t a2, uint32_t a3,
                                         float b0, float b1) {
    asm volatile(
        "mma.sync.aligned.m16n8k8.row.col.f32.tf32.tf32.f32 "
        "{%0,%1,%2,%3}, {%4,%5,%6,%7}, {%8,%9}, {%0,%1,%2,%3};"
        : "+f"(c[0]), "+f"(c[1]), "+f"(c[2]), "+f"(c[3])
        : "r"(a0), "r"(a1), "r"(a2), "r"(a3),
          "r"(__float_as_uint(b0)), "r"(__float_as_uint(b1)));
}

// ---------------------------------------------------------------------------
// Prep 1: kernel[b, i, o, k, l] (l fastest) -> g_kt[b][l][frag f]
// ---------------------------------------------------------------------------
__global__ void prep_kernel_tensor(const float* __restrict__ kin) {
    __shared__ float tile[32][33];
    int b  = blockIdx.z;
    int f0 = blockIdx.x * 32;
    int l0 = blockIdx.y * 32;
    int tx = threadIdx.x, ty = threadIdx.y;
    const float* src = kin + (size_t)b * 6144 * 128;
    float*       dst = g_kt + (size_t)b * 128 * 6144;
#pragma unroll
    for (int r = 0; r < 4; r++) {
        int f = f0 + ty + r * 8;
        int sub = f & 3, lane = (f >> 2) & 31, rest = f >> 7;
        int p = rest & 3, ks = rest >> 2;
        int tq = lane & 3, tr = lane >> 2;
        int kk = ks * 8 + tq + (sub & 1) * 4;
        int nt = 2 * p + (sub >> 1);
        int o  = nt * 8 + tr;
        int i  = kk / 3, k = kk - 3 * i;
        int m  = i * 192 + o * 3 + k;
        tile[ty + r * 8][tx] = tf32r(src[(size_t)m * 128 + l0 + tx]);
    }
    __syncthreads();
#pragma unroll
    for (int r = 0; r < 4; r++) {
        int l = l0 + ty + r * 8;
        dst[(size_t)l * 6144 + f0 + tx] = tile[tx][ty + r * 8];
    }
}

// Prep 2: conv_w [co][ci*3+k] -> g_w1f frag order (N=32 variant)
__global__ void prep_w1(const float* __restrict__ conv_w) {
    int f = blockIdx.x * 256 + threadIdx.x;
    if (f < 3072) {
        int sub = f & 3, lane = (f >> 2) & 31, rest = f >> 7;
        int p = rest & 1, ks = rest >> 1;
        int tq = lane & 3, tr = lane >> 2;
        int kk = ks * 8 + tq + (sub & 1) * 4;
        int nt = 2 * p + (sub >> 1);
        int co = nt * 8 + tr;
        g_w1f[f] = tf32r(conv_w[co * 96 + kk]);
    }
}

// ---------------------------------------------------------------------------
// Main fused kernel: one CTA per (256-position chunk, batch); 2 pipelined subs
// sharing ONE hs buffer (sub1 prefetch issued once sub0's hs is dead).
// ---------------------------------------------------------------------------
__global__ __launch_bounds__(256, 3)
void lvc_mma_kernel(const float* __restrict__ hidden,
                    const float* __restrict__ bias,
                    const float* __restrict__ conv_w,
                    const float* __restrict__ conv_b,
                    float* __restrict__ out) {
    extern __shared__ float sm[];
    float* wt1f  = sm + OF_WT1;
    float* wt2f  = sm + OF_WT2;
    float* biasS = sm + OF_BIAS;
    float* cbS   = sm + OF_CB;
    float* hsf   = sm + OF_HS;
    float* xsf   = sm + OF_XS;

    const int tid  = threadIdx.x;
    const int wid  = tid >> 5;
    const int lane = tid & 31;
    const int l    = blockIdx.x;      // 256-position chunk 0..127
    const int b    = blockIdx.y;
    const float* hidB = hidden + (size_t)b * HID * LEN;
    const uint32_t sb = smem_u32(sm);
    const uint32_t hbase = sb + OF_HS * 4;

    // ---- prefetch sub0's hs tile ----
    {
        const int s0p = l * 256;
        for (int idx = tid; idx < 1088; idx += 256) {
            int c = idx / 34, gr = idx - c * 34;
            int g = s0p - 4 + gr * 4;
            bool in = (g >= 0) && (g + 4 <= LEN);
            const float* src = hidB + (size_t)c * LEN + (in ? g : 0);
            cp_async16(hbase + (uint32_t)(c * HSS + gr * 4) * 4, src, in ? 16 : 0);
        }
        asm volatile("cp.async.commit_group;" ::: "memory");
    }

    // ---- stage weights (already tf32-rounded + frag-ordered) ----
    {
        const float4* w2s = (const float4*)(g_kt + ((size_t)b * KLCH + l) * 6144);
        float4* w2d = (float4*)wt2f;
        for (int i = tid; i < 1536; i += 256) w2d[i] = w2s[i];
        const float4* w1s = (const float4*)g_w1f;
        float4* w1d = (float4*)wt1f;
        for (int i = tid; i < 768; i += 256) w1d[i] = w1s[i];
    }
    if (tid < 64) biasS[tid] = bias[((size_t)b * 64 + tid) * KLCH + l];
    if (tid < 32) cbS[tid]   = conv_b[tid];

    const int tq = lane & 3;      // threadID_in_group
    const int tr = lane >> 4 ? (lane >> 2) & 7 : (lane >> 2);  // = lane>>2
    const int m0 = wid * 16;

#pragma unroll
    for (int s = 0; s < 2; s++) {
        const int s0 = l * 256 + s * 128;

        asm volatile("cp.async.wait_group 0;" ::: "memory");
        __syncthreads();

        // ---- in-place transform: leaky + tf32 round ----
        for (int idx = tid; idx < 1088; idx += 256) {
            int c = idx / 34, gr = idx - c * 34;
            float4* p = (float4*)(hsf + c * HSS + gr * 4);
            float4 t = *p;
            t.x = tf32r((t.x >= 0.f) ? t.x : 0.2f * t.x);
            t.y = tf32r((t.y >= 0.f) ? t.y : 0.2f * t.y);
            t.z = tf32r((t.z >= 0.f) ? t.z : 0.2f * t.z);
            t.w = tf32r((t.w >= 0.f) ? t.w : 0.2f * t.w);
            *p = t;
        }
        __syncthreads();

        // ---- Stage 1: conv GEMM, rows m=0..127 <-> p = s0-1+m ----
        {
            float c1[4][4];
#pragma unroll
            for (int nt = 0; nt < 4; nt++)
#pragma unroll
                for (int j = 0; j < 4; j++) c1[nt][j] = 0.f;

#pragma unroll
            for (int ks = 0; ks < 12; ks++) {
                int kk0 = ks * 8 + tq;
                int ci0 = kk0 / 3, kr0 = kk0 - ci0 * 3;
                int kk1 = kk0 + 4;
                int ci1 = kk1 / 3, kr1 = kk1 - ci1 * 3;
                int base = m0 + tr;
                uint32_t a0 = __float_as_uint(hsf[ci0 * HSS + base     + 3 * kr0]);
                uint32_t a1 = __float_as_uint(hsf[ci0 * HSS + base + 8 + 3 * kr0]);
                uint32_t a2 = __float_as_uint(hsf[ci1 * HSS + base     + 3 * kr1]);
                uint32_t a3 = __float_as_uint(hsf[ci1 * HSS + base + 8 + 3 * kr1]);
                const float4* bp = (const float4*)wt1f + (ks * 2) * 32 + lane;
                float4 q0 = bp[0];
                float4 q1 = bp[32];
                mma_tf32(c1[0], a0, a1, a2, a3, q0.x, q0.y);
                mma_tf32(c1[1], a0, a1, a2, a3, q0.z, q0.w);
                mma_tf32(c1[2], a0, a1, a2, a3, q1.x, q1.y);
                mma_tf32(c1[3], a0, a1, a2, a3, q1.z, q1.w);
            }
            bool z0 = (s0 == 0) && (m0 + tr == 0);
#pragma unroll
            for (int nt = 0; nt < 4; nt++) {
                int c = nt * 8 + 2 * tq;
                float v00 = c1[nt][0] + cbS[c];
                float v01 = c1[nt][1] + cbS[c + 1];
                float v10 = c1[nt][2] + cbS[c];
                float v11 = c1[nt][3] + cbS[c + 1];
                v00 = tf32r((v00 >= 0.f) ? v00 : 0.2f * v00);
                v01 = tf32r((v01 >= 0.f) ? v01 : 0.2f * v01);
                v10 = tf32r((v10 >= 0.f) ? v10 : 0.2f * v10);
                v11 = tf32r((v11 >= 0.f) ? v11 : 0.2f * v11);
                xsf[c       * XSS + m0 + tr]     = z0 ? 0.f : v00;
                xsf[(c + 1) * XSS + m0 + tr]     = z0 ? 0.f : v01;
                xsf[c       * XSS + m0 + tr + 8] = v10;
                xsf[(c + 1) * XSS + m0 + tr + 8] = v11;
            }
        }
        // ---- parallel tail rows m = 128, 129 (p = s0+127, s0+128): all 256 thr ----
        {
            int row = tid >> 7;            // 0,1
            int c   = (tid >> 2) & 31;
            int q   = tid & 3;
            int m   = 128 + row;
            // w1 frag address: wt1f[ks*256 + Cbase + tq*4 + hi]
            int ctr = c & 7, cnt = c >> 3;
            int Cbase = (cnt >> 1) * 128 + ctr * 16 + (cnt & 1) * 2;
            float acc = 0.f;
#pragma unroll
            for (int cc = 0; cc < 8; cc++) {
                int ci = q * 8 + cc;
                const float* hr = hsf + ci * HSS + m;
#pragma unroll
                for (int k = 0; k < 3; k++) {
                    int kk = 3 * ci + k;
                    int ksW = kk >> 3, rW = kk & 7;
                    float w = wt1f[ksW * 256 + Cbase + (rW & 3) * 4 + (rW >> 2)];
                    acc += w * hr[3 * k];
                }
            }
            acc += __shfl_xor_sync(0xffffffffu, acc, 1);
            acc += __shfl_xor_sync(0xffffffffu, acc, 2);
            if (q == 0) {
                float v = acc + cbS[c];
                v = tf32r((v >= 0.f) ? v : 0.2f * v);
                int p = s0 - 1 + m;
                xsf[c * XSS + m] = (p < LEN) ? v : 0.f;
            }
        }
        __syncthreads();

        // ---- hs is dead: prefetch next sub's hs into the SAME buffer ----
        if (s == 0) {
            const int s0p = l * 256 + 128;
            for (int idx = tid; idx < 1088; idx += 256) {
                int c = idx / 34, gr = idx - c * 34;
                int g = s0p - 4 + gr * 4;
                bool in = (g >= 0) && (g + 4 <= LEN);
                const float* src = hidB + (size_t)c * LEN + (in ? g : 0);
                cp_async16(hbase + (uint32_t)(c * HSS + gr * 4) * 4, src, in ? 16 : 0);
            }
            asm volatile("cp.async.commit_group;" ::: "memory");
        }

        // ---- Stage 2: LVC GEMM, rows m <-> s = s0+m ----
        float c2[8][4];
#pragma unroll
        for (int nt = 0; nt < 8; nt++)
#pragma unroll
            for (int j = 0; j < 4; j++) c2[nt][j] = 0.f;

#pragma unroll
        for (int ks = 0; ks < 12; ks++) {
            int kk0 = ks * 8 + tq;
            int i0 = kk0 / 3, kr0 = kk0 - i0 * 3;
            int kk1 = kk0 + 4;
            int i1 = kk1 / 3, kr1 = kk1 - i1 * 3;
            int base = m0 + tr;
            uint32_t a0 = __float_as_uint(xsf[i0 * XSS + base     + kr0]);
            uint32_t a1 = __float_as_uint(xsf[i0 * XSS + base + 8 + kr0]);
            uint32_t a2 = __float_as_uint(xsf[i1 * XSS + base     + kr1]);
            uint32_t a3 = __float_as_uint(xsf[i1 * XSS + base + 8 + kr1]);
            const float4* bp = (const float4*)wt2f + (ks * 4) * 32 + lane;
            float4 q0 = bp[0];
            float4 q1 = bp[32];
            float4 q2 = bp[64];
            float4 q3 = bp[96];
            mma_tf32(c2[0], a0, a1, a2, a3, q0.x, q0.y);
            mma_tf32(c2[1], a0, a1, a2, a3, q0.z, q0.w);
            mma_tf32(c2[2], a0, a1, a2, a3, q1.x, q1.y);
            mma_tf32(c2[3], a0, a1, a2, a3, q1.z, q1.w);
            mma_tf32(c2[4], a0, a1, a2, a3, q2.x, q2.y);
            mma_tf32(c2[5], a0, a1, a2, a3, q2.z, q2.w);
            mma_tf32(c2[6], a0, a1, a2, a3, q3.x, q3.y);
            mma_tf32(c2[7], a0, a1, a2, a3, q3.z, q3.w);
        }

        // ---- epilogue straight from fragments (sector-perfect 4B ops) ----
        {
            float* outB = out + (size_t)b * HID * LEN;
            const float LOG2E = 1.4426950408889634f;
#pragma unroll
            for (int nt = 0; nt < 4; nt++) {
                int o = nt * 8 + 2 * tq;
#pragma unroll
                for (int j = 0; j < 4; j++) {
                    int oo = o + (j & 1);
                    int m  = m0 + tr + ((j >> 1) << 3);
                    float gv = c2[nt][j]     + biasS[oo];
                    float hv = c2[nt + 4][j] + biasS[oo + 32];
                    float sig = fast_rcp(1.f + fast_ex2(-LOG2E * gv));
                    float res = hidB[(size_t)oo * LEN + s0 + m];
                    outB[(size_t)oo * LEN + s0 + m] = res + sig * fast_tanh(hv);
                }
            }
        }
    }
}

// ---------------------------------------------------------------------------
extern "C" void kernel_launch(void* const* d_in, const int* in_sizes, int n_in,
                              void* d_out, int out_size) {
    const float* hidden = (const float*)d_in[0];
    const float* kern   = (const float*)d_in[1];
    const float* bias   = (const float*)d_in[2];
    const float* conv_w = (const float*)d_in[3];
    const float* conv_b = (const float*)d_in[4];
    float* out = (float*)d_out;

    prep_w1<<<12, 256>>>(conv_w);
    prep_kernel_tensor<<<dim3(192, 4, 16), dim3(32, 8)>>>(kern);

    int smem_bytes = SMEM_FLOATS * 4;   // 71,552 B
    cudaFuncSetAttribute(lvc_mma_kernel,
                         cudaFuncAttributeMaxDynamicSharedMemorySize, smem_bytes);
    lvc_mma_kernel<<<dim3(KLCH, BATCH), 256, smem_bytes>>>(hidden, bias, conv_w, conv_b, out);
}

// round 9
// speedup vs baseline: 1.3460x; 1.3460x over previous
#include <cuda_runtime.h>
#include <cuda_fp16.h>
#include <stdint.h>

#define HID   32
#define LEN   32768
#define BATCH 16
#define KLCH  128

#define HSS 136     // hs row stride (fp32); 34 float4 granules per row
#define AS2 50      // A im2col row stride in u32 (half2) units; 50%32=18 -> conflict-free

// smem float offsets
#define OF_W1   0       // 1536 u32 : conv W frag order (fp16)
#define OF_W2   1536    // 3072 u32 : LVC W frag order (fp16)
#define OF_BIAS 4608    // 64
#define OF_CB   4672    // 32
#define OF_HS   4704    // 32 x 136 fp32 = 4352
#define OF_A    9056    // 130 x 50 u32 = 6500 (A1 / A2 im2col, half2)
#define SMEM_FLOATS 15556   // 62,224 bytes -> 3 CTA/SM

// weights pre-packed in m16n8k16 B-fragment order as half2-in-u32
__device__ __align__(16) uint32_t g_kth[(size_t)BATCH * KLCH * 3072];  // 25 MB
__device__ __align__(16) uint32_t g_w1h[1536];

__device__ __forceinline__ float fast_tanh(float x) { float r; asm("tanh.approx.f32 %0, %1;" : "=f"(r) : "f"(x)); return r; }
__device__ __forceinline__ float fast_ex2(float x)  { float r; asm("ex2.approx.f32 %0, %1;"  : "=f"(r) : "f"(x)); return r; }
__device__ __forceinline__ float fast_rcp(float x)  { float r; asm("rcp.approx.f32 %0, %1;"  : "=f"(r) : "f"(x)); return r; }
__device__ __forceinline__ float leaky(float x) { return (x >= 0.f) ? x : 0.2f * x; }

__device__ __forceinline__ uint32_t smem_u32p(const void* p) {
    uint32_t a; asm("{ .reg .u64 t; cvta.to.shared.u64 t, %1; cvt.u32.u64 %0, t; }" : "=r"(a) : "l"(p));
    return a;
}
__device__ __forceinline__ void cp_async16(uint32_t dst, const void* src, int src_bytes) {
    asm volatile("cp.async.ca.shared.global [%0], [%1], 16, %2;"
                 :: "r"(dst), "l"(src), "r"(src_bytes) : "memory");
}
__device__ __forceinline__ void mma_fp16(float c[4],
                                         uint32_t a0, uint32_t a1, uint32_t a2, uint32_t a3,
                                         uint32_t b0, uint32_t b1) {
    asm volatile(
        "mma.sync.aligned.m16n8k16.row.col.f32.f16.f16.f32 "
        "{%0,%1,%2,%3}, {%4,%5,%6,%7}, {%8,%9}, {%0,%1,%2,%3};"
        : "+f"(c[0]), "+f"(c[1]), "+f"(c[2]), "+f"(c[3])
        : "r"(a0), "r"(a1), "r"(a2), "r"(a3), "r"(b0), "r"(b1));
}
__device__ __forceinline__ uint32_t packh2(float lo, float hi) {
    __half2 h = __floats2half2_rn(lo, hi);
    return *reinterpret_cast<uint32_t*>(&h);
}

// scalar accessor into the stage-1 fragment-packed weights (tail rows only)
__device__ __forceinline__ float w1h_at(const uint32_t* w1, int c, int kk) {
    int ks = kk >> 4, k16 = kk & 15;
    int reg = k16 >> 3, tq = (k16 & 7) >> 1, lo = k16 & 1;
    int tr = c & 7, nt = c >> 3;
    int q = nt >> 1, j = ((nt & 1) << 1) | reg;
    uint32_t u = w1[(((ks * 2 + q) * 32) + (tq + 4 * tr)) * 4 + j];
    __half2 h2 = *reinterpret_cast<__half2*>(&u);
    return lo ? __high2float(h2) : __low2float(h2);
}

// ---------------------------------------------------------------------------
// Prep 1: kernel[b,i,o,k,l] -> g_kth[b][l][f] (u32 = half2, B-frag order, N=64)
// f = ((ks*4 + q)*32 + lane)*4 + j ; nt = 2q+(j>>1), reg = j&1
// lane=(tq,tr): n-col o = nt*8+tr ; k(lo) = ks*16 + 2tq + 8*reg
// ---------------------------------------------------------------------------
__global__ void prep_kernel_tensor(const float* __restrict__ kin) {
    __shared__ uint32_t tile[32][33];
    int b  = blockIdx.z;
    int f0 = blockIdx.x * 32;   // 96 blocks over f = 3072
    int l0 = blockIdx.y * 32;
    int tx = threadIdx.x, ty = threadIdx.y;
    const float* src = kin + (size_t)b * 6144 * 128;
    uint32_t*    dst = g_kth + (size_t)b * 128 * 3072;
#pragma unroll
    for (int r = 0; r < 4; r++) {
        int f = f0 + ty + r * 8;
        int j = f & 3, lane = (f >> 2) & 31, rest = f >> 7;
        int q = rest & 3, ks = rest >> 2;
        int tq = lane & 3, tr = lane >> 2;
        int nt = 2 * q + (j >> 1), reg = j & 1;
        int o  = nt * 8 + tr;
        int k0 = ks * 16 + 2 * tq + 8 * reg, k1 = k0 + 1;
        int i0 = k0 / 3, kt0 = k0 - 3 * i0;
        int i1 = k1 / 3, kt1 = k1 - 3 * i1;
        int mlo = i0 * 192 + o * 3 + kt0;
        int mhi = i1 * 192 + o * 3 + kt1;
        tile[ty + r * 8][tx] = packh2(src[(size_t)mlo * 128 + l0 + tx],
                                      src[(size_t)mhi * 128 + l0 + tx]);
    }
    __syncthreads();
#pragma unroll
    for (int r = 0; r < 4; r++) {
        int l = l0 + ty + r * 8;
        dst[(size_t)l * 3072 + f0 + tx] = tile[tx][ty + r * 8];
    }
}

// Prep 2: conv_w [co][ci*3+k] -> g_w1h frag order (N=32: q in {0,1})
__global__ void prep_w1(const float* __restrict__ conv_w) {
    int f = blockIdx.x * 256 + threadIdx.x;
    if (f < 1536) {
        int j = f & 3, lane = (f >> 2) & 31, rest = f >> 7;
        int q = rest & 1, ks = rest >> 1;
        int tq = lane & 3, tr = lane >> 2;
        int nt = 2 * q + (j >> 1), reg = j & 1;
        int co = nt * 8 + tr;
        int k0 = ks * 16 + 2 * tq + 8 * reg;
        g_w1h[f] = packh2(conv_w[co * 96 + k0], conv_w[co * 96 + k0 + 1]);
    }
}

// ---------------------------------------------------------------------------
// Main fused kernel: one CTA per (256-position chunk, batch); 2 pipelined subs.
// ---------------------------------------------------------------------------
__global__ __launch_bounds__(256, 3)
void lvc_mma_kernel(const float* __restrict__ hidden,
                    const float* __restrict__ bias,
                    const float* __restrict__ conv_w,
                    const float* __restrict__ conv_b,
                    float* __restrict__ out) {
    extern __shared__ float sm[];
    uint32_t* w1u   = (uint32_t*)(sm + OF_W1);
    uint32_t* w2u   = (uint32_t*)(sm + OF_W2);
    float*    biasS = sm + OF_BIAS;
    float*    cbS   = sm + OF_CB;
    float*    hsf   = sm + OF_HS;
    uint32_t* Au    = (uint32_t*)(sm + OF_A);
    __half*   Ah    = (__half*)Au;

    const int tid  = threadIdx.x;
    const int wid  = tid >> 5;
    const int lane = tid & 31;
    const int l    = blockIdx.x;      // 256-position chunk
    const int b    = blockIdx.y;
    const float* hidB = hidden + (size_t)b * HID * LEN;
    const uint32_t hbase = smem_u32p(hsf);

    // ---- prefetch sub0's hs tile (raw fp32) ----
    {
        const int s0p = l * 256;
        for (int idx = tid; idx < 1088; idx += 256) {
            int c = idx / 34, gr = idx - c * 34;
            int g = s0p - 4 + gr * 4;
            bool in = (g >= 0) && (g + 4 <= LEN);
            const float* src = hidB + (size_t)c * LEN + (in ? g : 0);
            cp_async16(hbase + (uint32_t)(c * HSS + gr * 4) * 4, src, in ? 16 : 0);
        }
        asm volatile("cp.async.commit_group;" ::: "memory");
    }

    // ---- stage weights (fp16, frag order) ----
    {
        const uint4* w2s = (const uint4*)(g_kth + ((size_t)b * KLCH + l) * 3072);
        uint4* w2d = (uint4*)w2u;
        for (int i = tid; i < 768; i += 256) w2d[i] = w2s[i];
        const uint4* w1s = (const uint4*)g_w1h;
        uint4* w1d = (uint4*)w1u;
        for (int i = tid; i < 384; i += 256) w1d[i] = w1s[i];
    }
    if (tid < 64) biasS[tid] = bias[((size_t)b * 64 + tid) * KLCH + l];
    if (tid < 32) cbS[tid]   = conv_b[tid];

    const int tq = lane & 3;
    const int tr = lane >> 2;
    const int m0 = wid * 16;

#pragma unroll
    for (int s = 0; s < 2; s++) {
        const int s0 = l * 256 + s * 128;

        asm volatile("cp.async.wait_group 0;" ::: "memory");
        __syncthreads();

        // ---- P1: build A1 im2col (half2): A1[m][jp] = (x[2jp], x[2jp+1]) ----
        // A1[m][ci*3+k] = leaky(hs[ci][m+3k])
#pragma unroll
        for (int t = 0; t < 24; t++) {
            int e = t * 256 + tid;
            int m = e & 127, jp = e >> 7;
            int kk0 = 2 * jp, kk1 = kk0 + 1;
            int ci0 = kk0 / 3, k0 = kk0 - 3 * ci0;
            int ci1 = kk1 / 3, k1 = kk1 - 3 * ci1;
            float v0 = leaky(hsf[ci0 * HSS + m + 3 * k0]);
            float v1 = leaky(hsf[ci1 * HSS + m + 3 * k1]);
            Au[m * AS2 + jp] = packh2(v0, v1);
        }
        __syncthreads();

        // ---- P2: stage-1 MMA (rows m=0..127 <-> p=s0-1+m) + tail compute ----
        float c1[4][4];
#pragma unroll
        for (int nt = 0; nt < 4; nt++)
#pragma unroll
            for (int j = 0; j < 4; j++) c1[nt][j] = 0.f;
#pragma unroll
        for (int ks = 0; ks < 6; ks++) {
            int jp = ks * 8 + tq;
            int rA = (m0 + tr) * AS2, rB = rA + 8 * AS2;
            uint32_t a0 = Au[rA + jp];
            uint32_t a1 = Au[rB + jp];
            uint32_t a2 = Au[rA + jp + 4];
            uint32_t a3 = Au[rB + jp + 4];
            const uint4* bp = (const uint4*)w1u + (ks * 2) * 32 + lane;
            uint4 q0 = bp[0];
            uint4 q1 = bp[32];
            mma_fp16(c1[0], a0, a1, a2, a3, q0.x, q0.y);
            mma_fp16(c1[1], a0, a1, a2, a3, q0.z, q0.w);
            mma_fp16(c1[2], a0, a1, a2, a3, q1.x, q1.y);
            mma_fp16(c1[3], a0, a1, a2, a3, q1.z, q1.w);
        }
        // tail conv rows u = 128,129 (parallel over all 256 threads)
        float tailv;
        {
            int row = tid >> 7;            // 0,1
            int c   = (tid >> 2) & 31;
            int q4  = tid & 3;
            int m   = 128 + row;
            float acc = 0.f;
#pragma unroll
            for (int cc = 0; cc < 8; cc++) {
                int ci = q4 * 8 + cc;
                const float* hr = hsf + ci * HSS + m;
#pragma unroll
                for (int k = 0; k < 3; k++)
                    acc += w1h_at(w1u, c, 3 * ci + k) * leaky(hr[3 * k]);
            }
            acc += __shfl_xor_sync(0xffffffffu, acc, 1);
            acc += __shfl_xor_sync(0xffffffffu, acc, 2);
            tailv = acc;
        }
        __syncthreads();   // A1 reads + hs reads complete

        // ---- P3: write A2 im2col (alias of A1): A2[m][3i+k] = xval(u=m+k) ----
#pragma unroll
        for (int nt = 0; nt < 4; nt++) {
#pragma unroll
            for (int j = 0; j < 4; j++) {
                int c = nt * 8 + 2 * tq + (j & 1);
                int u = m0 + tr + ((j >> 1) << 3);
                float v = leaky(c1[nt][j] + cbS[c]);
                __half h = (s0 == 0 && u == 0) ? __half(0.f) : __float2half_rn(v);
                Ah[u * (2 * AS2) + 3 * c] = h;
                if (u >= 1) Ah[(u - 1) * (2 * AS2) + 3 * c + 1] = h;
                if (u >= 2) Ah[(u - 2) * (2 * AS2) + 3 * c + 2] = h;
            }
        }
        if ((tid & 3) == 0) {   // tail rows u = 128,129
            int row = tid >> 7;
            int c   = (tid >> 2) & 31;
            int u   = 128 + row;
            float v = leaky(tailv + cbS[c]);
            int p = s0 - 1 + u;
            __half h = (p < LEN) ? __float2half_rn(v) : __half(0.f);
#pragma unroll
            for (int k = 1; k < 3; k++) {
                int r = u - k;
                if (r <= 127) Ah[r * (2 * AS2) + 3 * c + k] = h;
            }
        }
        // hs dead: prefetch next sub's tile into the same buffer
        if (s == 0) {
            const int s0p = l * 256 + 128;
            for (int idx = tid; idx < 1088; idx += 256) {
                int c = idx / 34, gr = idx - c * 34;
                int g = s0p - 4 + gr * 4;
                bool in = (g >= 0) && (g + 4 <= LEN);
                const float* src = hidB + (size_t)c * LEN + (in ? g : 0);
                cp_async16(hbase + (uint32_t)(c * HSS + gr * 4) * 4, src, in ? 16 : 0);
            }
            asm volatile("cp.async.commit_group;" ::: "memory");
        }
        __syncthreads();

        // ---- P4: stage-2 MMA (rows m <-> s = s0+m), N=64 ----
        float c2[8][4];
#pragma unroll
        for (int nt = 0; nt < 8; nt++)
#pragma unroll
            for (int j = 0; j < 4; j++) c2[nt][j] = 0.f;
#pragma unroll
        for (int ks = 0; ks < 6; ks++) {
            int jp = ks * 8 + tq;
            int rA = (m0 + tr) * AS2, rB = rA + 8 * AS2;
            uint32_t a0 = Au[rA + jp];
            uint32_t a1 = Au[rB + jp];
            uint32_t a2 = Au[rA + jp + 4];
            uint32_t a3 = Au[rB + jp + 4];
            const uint4* bp = (const uint4*)w2u + (ks * 4) * 32 + lane;
            uint4 q0 = bp[0];
            uint4 q1 = bp[32];
            uint4 q2 = bp[64];
            uint4 q3 = bp[96];
            mma_fp16(c2[0], a0, a1, a2, a3, q0.x, q0.y);
            mma_fp16(c2[1], a0, a1, a2, a3, q0.z, q0.w);
            mma_fp16(c2[2], a0, a1, a2, a3, q1.x, q1.y);
            mma_fp16(c2[3], a0, a1, a2, a3, q1.z, q1.w);
            mma_fp16(c2[4], a0, a1, a2, a3, q2.x, q2.y);
            mma_fp16(c2[5], a0, a1, a2, a3, q2.z, q2.w);
            mma_fp16(c2[6], a0, a1, a2, a3, q3.x, q3.y);
            mma_fp16(c2[7], a0, a1, a2, a3, q3.z, q3.w);
        }

        // ---- epilogue straight from fragments ----
        {
            float* outB = out + (size_t)b * HID * LEN;
            const float LOG2E = 1.4426950408889634f;
#pragma unroll
            for (int nt = 0; nt < 4; nt++) {
                int o = nt * 8 + 2 * tq;
#pragma unroll
                for (int j = 0; j < 4; j++) {
                    int oo = o + (j & 1);
                    int m  = m0 + tr + ((j >> 1) << 3);
                    float gv = c2[nt][j]     + biasS[oo];
                    float hv = c2[nt + 4][j] + biasS[oo + 32];
                    float sig = fast_rcp(1.f + fast_ex2(-LOG2E * gv));
                    float res = hidB[(size_t)oo * LEN + s0 + m];
                    outB[(size_t)oo * LEN + s0 + m] = res + sig * fast_tanh(hv);
                }
            }
        }
    }
}

// ---------------------------------------------------------------------------
extern "C" void kernel_launch(void* const* d_in, const int* in_sizes, int n_in,
                              void* d_out, int out_size) {
    const float* hidden = (const float*)d_in[0];
    const float* kern   = (const float*)d_in[1];
    const float* bias   = (const float*)d_in[2];
    const float* conv_w = (const float*)d_in[3];
    const float* conv_b = (const float*)d_in[4];
    float* out = (float*)d_out;

    prep_w1<<<6, 256>>>(conv_w);
    prep_kernel_tensor<<<dim3(96, 4, 16), dim3(32, 8)>>>(kern);

    int smem_bytes = SMEM_FLOATS * 4;   // 62,224 B
    cudaFuncSetAttribute(lvc_mma_kernel,
                         cudaFuncAttributeMaxDynamicSharedMemorySize, smem_bytes);
    lvc_mma_kernel<<<dim3(KLCH, BATCH), 256, smem_bytes>>>(hidden, bias, conv_w, conv_b, out);
}

// round 10
// speedup vs baseline: 1.6909x; 1.2563x over previous
#include <cuda_runtime.h>
#include <cuda_fp16.h>
#include <stdint.h>

#define HID   32
#define LEN   32768
#define BATCH 16
#define KLCH  128

#define HSS 136     // hs row stride (fp32 words)
#define TS  20      // hT/xT row stride in u32 (40 half); 20-stride -> conflict-free frags

// smem u32 offsets
#define OF_W1   0       // 1536 : conv W, per-shift frag order (half2)
#define OF_W2   1536    // 3072 : LVC W, per-shift frag order (half2)
#define OF_BIAS 4608    // 64 (fp32)
#define OF_CB   4672    // 32 (fp32)
#define OF_HS0  4704    // 4352 : raw fp32 hidden tile, buffer 0
#define OF_HS1  9056    // 4352 : buffer 1
#define OF_HT   13408   // 2720 : hT[136][40 half] leaky(h) fp16
#define OF_XT   16128   // 2600 : xT[130][40 half] stage-1 output fp16
#define SMEM_U32 18728  // 74,912 B -> 3 CTA/SM

// weights pre-packed per-shift (k=0..2), K=32, m16n8k16 B-frag order, half2-in-u32
__device__ __align__(16) uint32_t g_kth[(size_t)BATCH * KLCH * 3072];  // 25 MB
__device__ __align__(16) uint32_t g_w1h[1536];

__device__ __forceinline__ float fast_tanh(float x) { float r; asm("tanh.approx.f32 %0, %1;" : "=f"(r) : "f"(x)); return r; }
__device__ __forceinline__ float fast_ex2(float x)  { float r; asm("ex2.approx.f32 %0, %1;"  : "=f"(r) : "f"(x)); return r; }
__device__ __forceinline__ float fast_rcp(float x)  { float r; asm("rcp.approx.f32 %0, %1;"  : "=f"(r) : "f"(x)); return r; }
__device__ __forceinline__ float leaky(float x) { return (x >= 0.f) ? x : 0.2f * x; }

__device__ __forceinline__ uint32_t smem_u32p(const void* p) {
    uint32_t a; asm("{ .reg .u64 t; cvta.to.shared.u64 t, %1; cvt.u32.u64 %0, t; }" : "=r"(a) : "l"(p));
    return a;
}
__device__ __forceinline__ void cp_async16(uint32_t dst, const void* src, int src_bytes) {
    asm volatile("cp.async.ca.shared.global [%0], [%1], 16, %2;"
                 :: "r"(dst), "l"(src), "r"(src_bytes) : "memory");
}
__device__ __forceinline__ void mma_fp16(float c[4],
                                         uint32_t a0, uint32_t a1, uint32_t a2, uint32_t a3,
                                         uint32_t b0, uint32_t b1) {
    asm volatile(
        "mma.sync.aligned.m16n8k16.row.col.f32.f16.f16.f32 "
        "{%0,%1,%2,%3}, {%4,%5,%6,%7}, {%8,%9}, {%0,%1,%2,%3};"
        : "+f"(c[0]), "+f"(c[1]), "+f"(c[2]), "+f"(c[3])
        : "r"(a0), "r"(a1), "r"(a2), "r"(a3), "r"(b0), "r"(b1));
}
__device__ __forceinline__ uint32_t packh2(float lo, float hi) {
    __half2 h = __floats2half2_rn(lo, hi);
    return *reinterpret_cast<uint32_t*>(&h);
}

// scalar accessor: W1 shift-frag layout, element W1k[c][ci] (tail rows only)
__device__ __forceinline__ float w1k_at(const uint32_t* w1, int k, int c, int ci) {
    int ks = ci >> 4, r = ci & 15;
    int reg = r >> 3, rr = r & 7, tq = rr >> 1, lo = rr & 1;
    int tr = c & 7, nt = c >> 3;
    int q = nt >> 1, j = ((nt & 1) << 1) | reg;
    uint32_t u = w1[k * 512 + (((ks * 2 + q) * 32) + (tq + 4 * tr)) * 4 + j];
    __half2 h2 = *reinterpret_cast<__half2*>(&u);
    return lo ? __high2float(h2) : __low2float(h2);
}

// ---------------------------------------------------------------------------
// Prep: kernel[b,i,o,k,l] -> g_kth[b][l][k*1024 + f2]  (per-shift B-frag order)
// Also (block 0,0,0) packs conv_w -> g_w1h[k*512 + f1].
// ---------------------------------------------------------------------------
__global__ void prep_weights(const float* __restrict__ kin,
                             const float* __restrict__ conv_w) {
    __shared__ uint32_t tile[32][33];
    int b  = blockIdx.z;
    int f0 = blockIdx.x * 32;   // 96 blocks over f = 3072
    int l0 = blockIdx.y * 32;
    int tx = threadIdx.x, ty = threadIdx.y;
    const float* src = kin + (size_t)b * 6144 * 128;
    uint32_t*    dst = g_kth + (size_t)b * 128 * 3072;
#pragma unroll
    for (int r = 0; r < 4; r++) {
        int f = f0 + ty + r * 8;
        int k = f >> 10, f2 = f & 1023;
        int j = f2 & 3, lane = (f2 >> 2) & 31, blk = f2 >> 7;  // blk = ks*4+q
        int q = blk & 3, ks = blk >> 2;
        int tq = lane & 3, tr = lane >> 2;
        int nt = 2 * q + (j >> 1), reg = j & 1;
        int o  = nt * 8 + tr;
        int ci0 = ks * 16 + 2 * tq + 8 * reg;
        int mlo = ci0 * 192 + o * 3 + k;
        int mhi = (ci0 + 1) * 192 + o * 3 + k;
        tile[ty + r * 8][tx] = packh2(src[(size_t)mlo * 128 + l0 + tx],
                                      src[(size_t)mhi * 128 + l0 + tx]);
    }
    __syncthreads();
#pragma unroll
    for (int r = 0; r < 4; r++) {
        int l = l0 + ty + r * 8;
        dst[(size_t)l * 3072 + f0 + tx] = tile[tx][ty + r * 8];
    }
    // fold in conv-W packing (one block)
    if (blockIdx.x == 0 && blockIdx.y == 0 && blockIdx.z == 0) {
        int t = ty * 32 + tx;
        for (int f = t; f < 1536; f += 256) {
            int k = f >> 9, f1 = f & 511;
            int j = f1 & 3, lane = (f1 >> 2) & 31, blk = f1 >> 7;  // blk = ks*2+q
            int q = blk & 1, ks = blk >> 1;
            int tq = lane & 3, tr = lane >> 2;
            int nt = 2 * q + (j >> 1), reg = j & 1;
            int co = nt * 8 + tr;
            int ci0 = ks * 16 + 2 * tq + 8 * reg;
            g_w1h[f] = packh2(conv_w[co * 96 + 3 * ci0 + k],
                              conv_w[co * 96 + 3 * (ci0 + 1) + k]);
        }
    }
}

// ---------------------------------------------------------------------------
// Main fused kernel: one CTA per (256-position chunk, batch); 2 pipelined subs.
// ---------------------------------------------------------------------------
__global__ __launch_bounds__(256, 3)
void lvc_mma_kernel(const float* __restrict__ hidden,
                    const float* __restrict__ bias,
                    const float* __restrict__ conv_w,
                    const float* __restrict__ conv_b,
                    float* __restrict__ out) {
    extern __shared__ float sm[];
    uint32_t* w1u   = (uint32_t*)(sm + OF_W1);
    uint32_t* w2u   = (uint32_t*)(sm + OF_W2);
    float*    biasS = sm + OF_BIAS;
    float*    cbS   = sm + OF_CB;
    float*    hs0   = sm + OF_HS0;
    float*    hs1   = sm + OF_HS1;
    uint32_t* hTu   = (uint32_t*)(sm + OF_HT);
    __half*   hTh   = (__half*)hTu;
    uint32_t* xTu   = (uint32_t*)(sm + OF_XT);
    __half*   xTh   = (__half*)xTu;

    const int tid  = threadIdx.x;
    const int wid  = tid >> 5;
    const int lane = tid & 31;
    const int l    = blockIdx.x;
    const int b    = blockIdx.y;
    const float* hidB = hidden + (size_t)b * HID * LEN;
    const uint32_t hb0 = smem_u32p(hs0);
    const uint32_t hb1 = smem_u32p(hs1);

    // ---- prefetch sub0's hs tile (raw fp32) into buffer 0 ----
    {
        const int s0p = l * 256;
        for (int idx = tid; idx < 1088; idx += 256) {
            int c = idx / 34, gr = idx - c * 34;
            int g = s0p - 4 + gr * 4;
            bool in = (g >= 0) && (g + 4 <= LEN);
            const float* src = hidB + (size_t)c * LEN + (in ? g : 0);
            cp_async16(hb0 + (uint32_t)(c * HSS + gr * 4) * 4, src, in ? 16 : 0);
        }
        asm volatile("cp.async.commit_group;" ::: "memory");
    }

    // ---- stage weights ----
    {
        const uint4* w2s = (const uint4*)(g_kth + ((size_t)b * KLCH + l) * 3072);
        uint4* w2d = (uint4*)w2u;
        for (int i = tid; i < 768; i += 256) w2d[i] = w2s[i];
        const uint4* w1s = (const uint4*)g_w1h;
        uint4* w1d = (uint4*)w1u;
        for (int i = tid; i < 384; i += 256) w1d[i] = w1s[i];
    }
    if (tid < 64) biasS[tid] = bias[((size_t)b * 64 + tid) * KLCH + l];
    if (tid < 32) cbS[tid]   = conv_b[tid];

    const int tq = lane & 3;
    const int tr = lane >> 2;
    const int m0 = wid * 16;

#pragma unroll
    for (int s = 0; s < 2; s++) {
        const int s0 = l * 256 + s * 128;
        float* hscur = s ? hs1 : hs0;

        asm volatile("cp.async.wait_group 0;" ::: "memory");
        __syncthreads();

        // issue next sub's prefetch immediately (into the other buffer)
        if (s == 0) {
            const int s0p = l * 256 + 128;
            for (int idx = tid; idx < 1088; idx += 256) {
                int c = idx / 34, gr = idx - c * 34;
                int g = s0p - 4 + gr * 4;
                bool in = (g >= 0) && (g + 4 <= LEN);
                const float* src = hidB + (size_t)c * LEN + (in ? g : 0);
                cp_async16(hb1 + (uint32_t)(c * HSS + gr * 4) * 4, src, in ? 16 : 0);
            }
            asm volatile("cp.async.commit_group;" ::: "memory");
        }

        // ---- P1: build hT[v][c] = half(leaky(hs[c][v])) ----
#pragma unroll
        for (int t = 0; t < 17; t++) {
            int idx = t * 256 + tid;
            int v = idx >> 5, c = idx & 31;
            hTh[v * 40 + c] = __float2half_rn(leaky(hscur[c * HSS + v]));
        }
        __syncthreads();

        // ---- P2: stage-1 shift-GEMM (3 shifts x K=32), rows m <-> p = s0-1+m ----
        float c1[4][4];
#pragma unroll
        for (int nt = 0; nt < 4; nt++)
#pragma unroll
            for (int j = 0; j < 4; j++) c1[nt][j] = 0.f;

        const uint4* w1q = (const uint4*)w1u;
#pragma unroll
        for (int k = 0; k < 3; k++) {
#pragma unroll
            for (int ks = 0; ks < 2; ks++) {
                int r = (m0 + tr + 3 * k) * TS + ks * 8 + tq;
                uint32_t a0 = hTu[r];
                uint32_t a1 = hTu[r + 8 * TS];
                uint32_t a2 = hTu[r + 4];
                uint32_t a3 = hTu[r + 8 * TS + 4];
                uint4 q0 = w1q[k * 128 + ks * 64 + lane];
                uint4 q1 = w1q[k * 128 + ks * 64 + 32 + lane];
                mma_fp16(c1[0], a0, a1, a2, a3, q0.x, q0.y);
                mma_fp16(c1[1], a0, a1, a2, a3, q0.z, q0.w);
                mma_fp16(c1[2], a0, a1, a2, a3, q1.x, q1.y);
                mma_fp16(c1[3], a0, a1, a2, a3, q1.z, q1.w);
            }
        }
        // tail conv rows u = 128,129 (parallel over all 256 threads, raw hs)
        float tailv;
        {
            int row = tid >> 7;            // 0,1
            int c   = (tid >> 2) & 31;
            int q4  = tid & 3;
            int m   = 128 + row;
            float acc = 0.f;
#pragma unroll
            for (int cc = 0; cc < 8; cc++) {
                int ci = q4 * 8 + cc;
                const float* hr = hscur + ci * HSS + m;
#pragma unroll
                for (int k = 0; k < 3; k++)
                    acc += w1k_at(w1u, k, c, ci) * leaky(hr[3 * k]);
            }
            acc += __shfl_xor_sync(0xffffffffu, acc, 1);
            acc += __shfl_xor_sync(0xffffffffu, acc, 2);
            tailv = acc;
        }

        // ---- P3: write xT[u][c] (single half store per value) ----
#pragma unroll
        for (int nt = 0; nt < 4; nt++) {
#pragma unroll
            for (int j = 0; j < 4; j++) {
                int c = nt * 8 + 2 * tq + (j & 1);
                int u = m0 + tr + ((j >> 1) << 3);
                float v = leaky(c1[nt][j] + cbS[c]);
                xTh[u * 40 + c] = (s0 == 0 && u == 0) ? __half(0.f)
                                                      : __float2half_rn(v);
            }
        }
        if ((tid & 3) == 0) {   // tail rows u = 128,129
            int row = tid >> 7;
            int c   = (tid >> 2) & 31;
            int u   = 128 + row;
            float v = leaky(tailv + cbS[c]);
            int p = s0 - 1 + u;
            xTh[u * 40 + c] = (p < LEN) ? __float2half_rn(v) : __half(0.f);
        }
        __syncthreads();

        // ---- P4: stage-2 shift-GEMM (3 shifts x K=32), N=64, rows m <-> s0+m ----
        float c2[8][4];
#pragma unroll
        for (int nt = 0; nt < 8; nt++)
#pragma unroll
            for (int j = 0; j < 4; j++) c2[nt][j] = 0.f;

        const uint4* w2q = (const uint4*)w2u;
#pragma unroll
        for (int k = 0; k < 3; k++) {
#pragma unroll
            for (int ks = 0; ks < 2; ks++) {
                int r = (m0 + tr + k) * TS + ks * 8 + tq;
                uint32_t a0 = xTu[r];
                uint32_t a1 = xTu[r + 8 * TS];
                uint32_t a2 = xTu[r + 4];
                uint32_t a3 = xTu[r + 8 * TS + 4];
                int bi = k * 256 + ks * 128 + lane;
                uint4 q0 = w2q[bi];
                uint4 q1 = w2q[bi + 32];
                uint4 q2 = w2q[bi + 64];
                uint4 q3 = w2q[bi + 96];
                mma_fp16(c2[0], a0, a1, a2, a3, q0.x, q0.y);
                mma_fp16(c2[1], a0, a1, a2, a3, q0.z, q0.w);
                mma_fp16(c2[2], a0, a1, a2, a3, q1.x, q1.y);
                mma_fp16(c2[3], a0, a1, a2, a3, q1.z, q1.w);
                mma_fp16(c2[4], a0, a1, a2, a3, q2.x, q2.y);
                mma_fp16(c2[5], a0, a1, a2, a3, q2.z, q2.w);
                mma_fp16(c2[6], a0, a1, a2, a3, q3.x, q3.y);
                mma_fp16(c2[7], a0, a1, a2, a3, q3.z, q3.w);
            }
        }

        // ---- epilogue: gate + residual (residual from raw hs in smem) ----
        {
            float* outB = out + (size_t)b * HID * LEN;
            const float LOG2E = 1.4426950408889634f;
#pragma unroll
            for (int nt = 0; nt < 4; nt++) {
                int o = nt * 8 + 2 * tq;
#pragma unroll
                for (int j = 0; j < 4; j++) {
                    int oo = o + (j & 1);
                    int m  = m0 + tr + ((j >> 1) << 3);
                    float gv = c2[nt][j]     + biasS[oo];
                    float hv = c2[nt + 4][j] + biasS[oo + 32];
                    float sig = fast_rcp(1.f + fast_ex2(-LOG2E * gv));
                    float res = hscur[oo * HSS + m + 4];
                    outB[(size_t)oo * LEN + s0 + m] = res + sig * fast_tanh(hv);
                }
            }
        }
    }
}

// ---------------------------------------------------------------------------
extern "C" void kernel_launch(void* const* d_in, const int* in_sizes, int n_in,
                              void* d_out, int out_size) {
    const float* hidden = (const float*)d_in[0];
    const float* kern   = (const float*)d_in[1];
    const float* bias   = (const float*)d_in[2];
    const float* conv_w = (const float*)d_in[3];
    const float* conv_b = (const float*)d_in[4];
    float* out = (float*)d_out;

    prep_weights<<<dim3(96, 4, 16), dim3(32, 8)>>>(kern, conv_w);

    int smem_bytes = SMEM_U32 * 4;   // 74,912 B
    cudaFuncSetAttribute(lvc_mma_kernel,
                         cudaFuncAttributeMaxDynamicSharedMemorySize, smem_bytes);
    lvc_mma_kernel<<<dim3(KLCH, BATCH), 256, smem_bytes>>>(hidden, bias, conv_w, conv_b, out);
}

// round 11
// speedup vs baseline: 2.2033x; 1.3031x over previous
#include <cuda_runtime.h>
#include <cuda_fp16.h>
#include <stdint.h>

#define HID   32
#define LEN   32768
#define BATCH 16
#define KLCH  128

#define HSS 136     // hs row stride (fp32 words)
#define TS  20      // hT/xT row stride in u32 (40 half)

// smem u32 offsets
#define OF_W1   0       // 1536 : conv W, per-shift frag order (half2)
#define OF_W2   1536    // 3072 : LVC W, per-shift frag order (half2)
#define OF_BIAS 4608    // 64 (fp32)
#define OF_CB   4672    // 32 (fp32)
#define OF_HS0  4704    // 4352 : raw fp32 hidden tile, buffer 0
#define OF_HS1  9056    // 4352 : buffer 1
#define OF_HT   13408   // 3040 : hT[152][40 half]; rows 136..151 zero
#define OF_XT   16448   // 2600 : xT[130][40 half]
#define SMEM_U32 19048  // 76,192 B -> 3 CTA/SM

// weights pre-packed per-shift (k=0..2), K=32, m16n8k16 B-frag order, half2-in-u32
__device__ __align__(16) uint32_t g_kth[(size_t)BATCH * KLCH * 3072];  // 25 MB
__device__ __align__(16) uint32_t g_w1h[1536];

__device__ __forceinline__ float fast_tanh(float x) { float r; asm("tanh.approx.f32 %0, %1;" : "=f"(r) : "f"(x)); return r; }
__device__ __forceinline__ float fast_ex2(float x)  { float r; asm("ex2.approx.f32 %0, %1;"  : "=f"(r) : "f"(x)); return r; }
__device__ __forceinline__ float fast_rcp(float x)  { float r; asm("rcp.approx.f32 %0, %1;"  : "=f"(r) : "f"(x)); return r; }
__device__ __forceinline__ float leaky(float x) { return (x >= 0.f) ? x : 0.2f * x; }

__device__ __forceinline__ uint32_t smem_u32p(const void* p) {
    uint32_t a; asm("{ .reg .u64 t; cvta.to.shared.u64 t, %1; cvt.u32.u64 %0, t; }" : "=r"(a) : "l"(p));
    return a;
}
__device__ __forceinline__ void cp_async16(uint32_t dst, const void* src, int src_bytes) {
    asm volatile("cp.async.ca.shared.global [%0], [%1], 16, %2;"
                 :: "r"(dst), "l"(src), "r"(src_bytes) : "memory");
}
__device__ __forceinline__ void mma_fp16(float c[4],
                                         uint32_t a0, uint32_t a1, uint32_t a2, uint32_t a3,
                                         uint32_t b0, uint32_t b1) {
    asm volatile(
        "mma.sync.aligned.m16n8k16.row.col.f32.f16.f16.f32 "
        "{%0,%1,%2,%3}, {%4,%5,%6,%7}, {%8,%9}, {%0,%1,%2,%3};"
        : "+f"(c[0]), "+f"(c[1]), "+f"(c[2]), "+f"(c[3])
        : "r"(a0), "r"(a1), "r"(a2), "r"(a3), "r"(b0), "r"(b1));
}
__device__ __forceinline__ uint32_t packh2(float lo, float hi) {
    __half2 h = __floats2half2_rn(lo, hi);
    return *reinterpret_cast<uint32_t*>(&h);
}

// ---------------------------------------------------------------------------
// Prep: kernel[b,i,o,k,l] -> g_kth[b][l][k*1024 + f2]  (per-shift B-frag order)
// Also (block 0,0,0) packs conv_w -> g_w1h[k*512 + f1].
// ---------------------------------------------------------------------------
__global__ void prep_weights(const float* __restrict__ kin,
                             const float* __restrict__ conv_w) {
    __shared__ uint32_t tile[32][33];
    int b  = blockIdx.z;
    int f0 = blockIdx.x * 32;   // 96 blocks over f = 3072
    int l0 = blockIdx.y * 32;
    int tx = threadIdx.x, ty = threadIdx.y;
    const float* src = kin + (size_t)b * 6144 * 128;
    uint32_t*    dst = g_kth + (size_t)b * 128 * 3072;
#pragma unroll
    for (int r = 0; r < 4; r++) {
        int f = f0 + ty + r * 8;
        int k = f >> 10, f2 = f & 1023;
        int j = f2 & 3, lane = (f2 >> 2) & 31, blk = f2 >> 7;  // blk = ks*4+q
        int q = blk & 3, ks = blk >> 2;
        int tq = lane & 3, tr = lane >> 2;
        int nt = 2 * q + (j >> 1), reg = j & 1;
        int o  = nt * 8 + tr;
        int ci0 = ks * 16 + 2 * tq + 8 * reg;
        int mlo = ci0 * 192 + o * 3 + k;
        int mhi = (ci0 + 1) * 192 + o * 3 + k;
        tile[ty + r * 8][tx] = packh2(src[(size_t)mlo * 128 + l0 + tx],
                                      src[(size_t)mhi * 128 + l0 + tx]);
    }
    __syncthreads();
#pragma unroll
    for (int r = 0; r < 4; r++) {
        int l = l0 + ty + r * 8;
        dst[(size_t)l * 3072 + f0 + tx] = tile[tx][ty + r * 8];
    }
    if (blockIdx.x == 0 && blockIdx.y == 0 && blockIdx.z == 0) {
        int t = ty * 32 + tx;
        for (int f = t; f < 1536; f += 256) {
            int k = f >> 9, f1 = f & 511;
            int j = f1 & 3, lane = (f1 >> 2) & 31, blk = f1 >> 7;  // blk = ks*2+q
            int q = blk & 1, ks = blk >> 1;
            int tq = lane & 3, tr = lane >> 2;
            int nt = 2 * q + (j >> 1), reg = j & 1;
            int co = nt * 8 + tr;
            int ci0 = ks * 16 + 2 * tq + 8 * reg;
            g_w1h[f] = packh2(conv_w[co * 96 + 3 * ci0 + k],
                              conv_w[co * 96 + 3 * (ci0 + 1) + k]);
        }
    }
}

// ---------------------------------------------------------------------------
// Main fused kernel: one CTA per (256-position chunk, batch); 2 pipelined subs.
// ---------------------------------------------------------------------------
__global__ __launch_bounds__(256, 3)
void lvc_mma_kernel(const float* __restrict__ hidden,
                    const float* __restrict__ bias,
                    const float* __restrict__ conv_w,
                    const float* __restrict__ conv_b,
                    float* __restrict__ out) {
    extern __shared__ float sm[];
    uint32_t* w1u   = (uint32_t*)(sm + OF_W1);
    uint32_t* w2u   = (uint32_t*)(sm + OF_W2);
    float*    biasS = sm + OF_BIAS;
    float*    cbS   = sm + OF_CB;
    float*    hs0   = sm + OF_HS0;
    float*    hs1   = sm + OF_HS1;
    uint32_t* hTu   = (uint32_t*)(sm + OF_HT);
    uint32_t* xTu   = (uint32_t*)(sm + OF_XT);
    __half*   xTh   = (__half*)xTu;

    const int tid  = threadIdx.x;
    const int wid  = tid >> 5;
    const int lane = tid & 31;
    const int l    = blockIdx.x;
    const int b    = blockIdx.y;
    const float* hidB = hidden + (size_t)b * HID * LEN;
    const uint32_t hb0 = smem_u32p(hs0);
    const uint32_t hb1 = smem_u32p(hs1);

    // ---- prefetch sub0's hs tile (raw fp32) into buffer 0 ----
    {
        const int s0p = l * 256;
        for (int idx = tid; idx < 1088; idx += 256) {
            int c = idx / 34, gr = idx - c * 34;
            int g = s0p - 4 + gr * 4;
            bool in = (g >= 0) && (g + 4 <= LEN);
            const float* src = hidB + (size_t)c * LEN + (in ? g : 0);
            cp_async16(hb0 + (uint32_t)(c * HSS + gr * 4) * 4, src, in ? 16 : 0);
        }
        asm volatile("cp.async.commit_group;" ::: "memory");
    }

    // ---- stage weights; zero hT pad rows 136..151 ----
    {
        const uint4* w2s = (const uint4*)(g_kth + ((size_t)b * KLCH + l) * 3072);
        uint4* w2d = (uint4*)w2u;
        for (int i = tid; i < 768; i += 256) w2d[i] = w2s[i];
        const uint4* w1s = (const uint4*)g_w1h;
        uint4* w1d = (uint4*)w1u;
        for (int i = tid; i < 384; i += 256) w1d[i] = w1s[i];
        for (int i = tid; i < 320; i += 256) hTu[2720 + i] = 0;
    }
    if (tid < 64) biasS[tid] = bias[((size_t)b * 64 + tid) * KLCH + l];
    if (tid < 32) cbS[tid]   = conv_b[tid];

    const int tq = lane & 3;
    const int tr = lane >> 2;
    const int m0 = wid * 16;

#pragma unroll
    for (int s = 0; s < 2; s++) {
        const int s0 = l * 256 + s * 128;
        float* hscur = s ? hs1 : hs0;

        asm volatile("cp.async.wait_group 0;" ::: "memory");
        __syncthreads();

        // issue next sub's prefetch immediately (into the other buffer)
        if (s == 0) {
            const int s0p = l * 256 + 128;
            for (int idx = tid; idx < 1088; idx += 256) {
                int c = idx / 34, gr = idx - c * 34;
                int g = s0p - 4 + gr * 4;
                bool in = (g >= 0) && (g + 4 <= LEN);
                const float* src = hidB + (size_t)c * LEN + (in ? g : 0);
                cp_async16(hb1 + (uint32_t)(c * HSS + gr * 4) * 4, src, in ? 16 : 0);
            }
            asm volatile("cp.async.commit_group;" ::: "memory");
        }

        // ---- P1: build hT (half2-pack transpose, low-conflict) ----
        // word hT[v][ce] = (leaky(hs[2ce][v]), leaky(hs[2ce+1][v]))
#pragma unroll
        for (int t = 0; t < 8; t++) {
            int g  = t * 8 + wid;           // 0..63
            int ce = (g & 3) * 4 + (lane >> 3);
            int v  = (g >> 2) * 8 + (lane & 7);
            float lo = leaky(hscur[(2 * ce)     * HSS + v]);
            float hi = leaky(hscur[(2 * ce + 1) * HSS + v]);
            hTu[v * TS + ce] = packh2(lo, hi);
        }
        if (tid < 128) {                    // tail v = 128..135
            int ce = tid >> 3, vr = tid & 7, v = 128 + vr;
            float lo = leaky(hscur[(2 * ce)     * HSS + v]);
            float hi = leaky(hscur[(2 * ce + 1) * HSS + v]);
            hTu[v * TS + ce] = packh2(lo, hi);
        }
        __syncthreads();

        // ---- P2: stage-1 shift-GEMM (3 shifts x K=32), rows m <-> p = s0-1+m ----
        float c1[4][4];
#pragma unroll
        for (int nt = 0; nt < 4; nt++)
#pragma unroll
            for (int j = 0; j < 4; j++) c1[nt][j] = 0.f;

        const uint4* w1q = (const uint4*)w1u;
#pragma unroll
        for (int k = 0; k < 3; k++) {
#pragma unroll
            for (int ks = 0; ks < 2; ks++) {
                int r = (m0 + tr + 3 * k) * TS + ks * 8 + tq;
                uint32_t a0 = hTu[r];
                uint32_t a1 = hTu[r + 8 * TS];
                uint32_t a2 = hTu[r + 4];
                uint32_t a3 = hTu[r + 8 * TS + 4];
                uint4 q0 = w1q[k * 128 + ks * 64 + lane];
                uint4 q1 = w1q[k * 128 + ks * 64 + 32 + lane];
                mma_fp16(c1[0], a0, a1, a2, a3, q0.x, q0.y);
                mma_fp16(c1[1], a0, a1, a2, a3, q0.z, q0.w);
                mma_fp16(c1[2], a0, a1, a2, a3, q1.x, q1.y);
                mma_fp16(c1[3], a0, a1, a2, a3, q1.z, q1.w);
            }
        }

        // ---- P3: write xT[u][c] ----
#pragma unroll
        for (int nt = 0; nt < 4; nt++) {
#pragma unroll
            for (int j = 0; j < 4; j++) {
                int c = nt * 8 + 2 * tq + (j & 1);
                int u = m0 + tr + ((j >> 1) << 3);
                float v = leaky(c1[nt][j] + cbS[c]);
                xTh[u * 40 + c] = (s0 == 0 && u == 0) ? __half(0.f)
                                                      : __float2half_rn(v);
            }
        }
        // tail rows u = 128,129 via an extra MMA tile on warp 0 (c1 regs dead)
        if (wid == 0) {
            float c1b[4][4];
#pragma unroll
            for (int nt = 0; nt < 4; nt++)
#pragma unroll
                for (int j = 0; j < 4; j++) c1b[nt][j] = 0.f;
#pragma unroll
            for (int k = 0; k < 3; k++) {
#pragma unroll
                for (int ks = 0; ks < 2; ks++) {
                    int r = (128 + tr + 3 * k) * TS + ks * 8 + tq;
                    uint32_t a0 = hTu[r];
                    uint32_t a1 = hTu[r + 8 * TS];
                    uint32_t a2 = hTu[r + 4];
                    uint32_t a3 = hTu[r + 8 * TS + 4];
                    uint4 q0 = w1q[k * 128 + ks * 64 + lane];
                    uint4 q1 = w1q[k * 128 + ks * 64 + 32 + lane];
                    mma_fp16(c1b[0], a0, a1, a2, a3, q0.x, q0.y);
                    mma_fp16(c1b[1], a0, a1, a2, a3, q0.z, q0.w);
                    mma_fp16(c1b[2], a0, a1, a2, a3, q1.x, q1.y);
                    mma_fp16(c1b[3], a0, a1, a2, a3, q1.z, q1.w);
                }
            }
            if (tr < 2) {
                int u = 128 + tr;               // p = s0 + 127 + tr
                bool ok = (s0 + 127 + tr) < LEN;
#pragma unroll
                for (int nt = 0; nt < 4; nt++) {
#pragma unroll
                    for (int j = 0; j < 2; j++) {
                        int c = nt * 8 + 2 * tq + j;
                        float v = leaky(c1b[nt][j] + cbS[c]);
                        xTh[u * 40 + c] = ok ? __float2half_rn(v) : __half(0.f);
                    }
                }
            }
        }
        __syncthreads();

        // ---- P4: stage-2 shift-GEMM (3 shifts x K=32), N=64, rows m <-> s0+m ----
        float c2[8][4];
#pragma unroll
        for (int nt = 0; nt < 8; nt++)
#pragma unroll
            for (int j = 0; j < 4; j++) c2[nt][j] = 0.f;

        const uint4* w2q = (const uint4*)w2u;
#pragma unroll
        for (int k = 0; k < 3; k++) {
#pragma unroll
            for (int ks = 0; ks < 2; ks++) {
                int r = (m0 + tr + k) * TS + ks * 8 + tq;
                uint32_t a0 = xTu[r];
                uint32_t a1 = xTu[r + 8 * TS];
                uint32_t a2 = xTu[r + 4];
                uint32_t a3 = xTu[r + 8 * TS + 4];
                int bi = k * 256 + ks * 128 + lane;
                uint4 q0 = w2q[bi];
                uint4 q1 = w2q[bi + 32];
                uint4 q2 = w2q[bi + 64];
                uint4 q3 = w2q[bi + 96];
                mma_fp16(c2[0], a0, a1, a2, a3, q0.x, q0.y);
                mma_fp16(c2[1], a0, a1, a2, a3, q0.z, q0.w);
                mma_fp16(c2[2], a0, a1, a2, a3, q1.x, q1.y);
                mma_fp16(c2[3], a0, a1, a2, a3, q1.z, q1.w);
                mma_fp16(c2[4], a0, a1, a2, a3, q2.x, q2.y);
                mma_fp16(c2[5], a0, a1, a2, a3, q2.z, q2.w);
                mma_fp16(c2[6], a0, a1, a2, a3, q3.x, q3.y);
                mma_fp16(c2[7], a0, a1, a2, a3, q3.z, q3.w);
            }
        }

        // ---- epilogue: gate + residual (residual from raw hs in smem) ----
        {
            float* outB = out + (size_t)b * HID * LEN;
            const float LOG2E = 1.4426950408889634f;
#pragma unroll
            for (int nt = 0; nt < 4; nt++) {
                int o = nt * 8 + 2 * tq;
#pragma unroll
                for (int j = 0; j < 4; j++) {
                    int oo = o + (j & 1);
                    int m  = m0 + tr + ((j >> 1) << 3);
                    float gv = c2[nt][j]     + biasS[oo];
                    float hv = c2[nt + 4][j] + biasS[oo + 32];
                    float sig = fast_rcp(1.f + fast_ex2(-LOG2E * gv));
                    float res = hscur[oo * HSS + m + 4];
                    outB[(size_t)oo * LEN + s0 + m] = res + sig * fast_tanh(hv);
                }
            }
        }
    }
}

// ---------------------------------------------------------------------------
extern "C" void kernel_launch(void* const* d_in, const int* in_sizes, int n_in,
                              void* d_out, int out_size) {
    const float* hidden = (const float*)d_in[0];
    const float* kern   = (const float*)d_in[1];
    const float* bias   = (const float*)d_in[2];
    const float* conv_w = (const float*)d_in[3];
    const float* conv_b = (const float*)d_in[4];
    float* out = (float*)d_out;

    prep_weights<<<dim3(96, 4, 16), dim3(32, 8)>>>(kern, conv_w);

    int smem_bytes = SMEM_U32 * 4;   // 76,192 B
    cudaFuncSetAttribute(lvc_mma_kernel,
                         cudaFuncAttributeMaxDynamicSharedMemorySize, smem_bytes);
    lvc_mma_kernel<<<dim3(KLCH, BATCH), 256, smem_bytes>>>(hidden, bias, conv_w, conv_b, out);
}

// round 12
// speedup vs baseline: 2.2431x; 1.0181x over previous
#include <cuda_runtime.h>
#include <cuda_fp16.h>
#include <stdint.h>

#define HID   32
#define LEN   32768
#define BATCH 16
#define KLCH  128

#define HSS 136     // hs row stride (fp32 words)
#define TS  20      // hT/xT row stride in u32 (40 half)

// smem u32 offsets
#define OF_W1   0       // 1536 : conv W, per-shift frag order (half2)
#define OF_W2   1536    // 3072 : LVC W, per-shift frag order (half2)
#define OF_BIAS 4608    // 64 (fp32)
#define OF_CB   4672    // 32 (fp32)
#define OF_HS0  4704    // 4352 : raw fp32 hidden tile, buffer 0
#define OF_HS1  9056    // 4352 : buffer 1
#define OF_HT   13408   // 3040 : hT[152][40 half]; rows 136..151 zero
#define OF_XT   16448   // 2600 : xT[130][40 half]
#define SMEM_U32 19048  // 76,192 B -> 3 CTA/SM

// weights pre-packed per-shift (k=0..2), K=32, m16n8k16 B-frag order, half2-in-u32
__device__ __align__(16) uint32_t g_kth[(size_t)BATCH * KLCH * 3072];  // 25 MB
__device__ __align__(16) uint32_t g_w1h[1536];

__device__ __forceinline__ float fast_tanh(float x) { float r; asm("tanh.approx.f32 %0, %1;" : "=f"(r) : "f"(x)); return r; }
__device__ __forceinline__ float fast_ex2(float x)  { float r; asm("ex2.approx.f32 %0, %1;"  : "=f"(r) : "f"(x)); return r; }
__device__ __forceinline__ float fast_rcp(float x)  { float r; asm("rcp.approx.f32 %0, %1;"  : "=f"(r) : "f"(x)); return r; }
__device__ __forceinline__ float leaky(float x) { return (x >= 0.f) ? x : 0.2f * x; }

__device__ __forceinline__ uint32_t smem_u32p(const void* p) {
    uint32_t a; asm("{ .reg .u64 t; cvta.to.shared.u64 t, %1; cvt.u32.u64 %0, t; }" : "=r"(a) : "l"(p));
    return a;
}
__device__ __forceinline__ void cp_async16(uint32_t dst, const void* src, int src_bytes) {
    asm volatile("cp.async.ca.shared.global [%0], [%1], 16, %2;"
                 :: "r"(dst), "l"(src), "r"(src_bytes) : "memory");
}
__device__ __forceinline__ void mma_fp16(float c[4],
                                         uint32_t a0, uint32_t a1, uint32_t a2, uint32_t a3,
                                         uint32_t b0, uint32_t b1) {
    asm volatile(
        "mma.sync.aligned.m16n8k16.row.col.f32.f16.f16.f32 "
        "{%0,%1,%2,%3}, {%4,%5,%6,%7}, {%8,%9}, {%0,%1,%2,%3};"
        : "+f"(c[0]), "+f"(c[1]), "+f"(c[2]), "+f"(c[3])
        : "r"(a0), "r"(a1), "r"(a2), "r"(a3), "r"(b0), "r"(b1));
}
// ldmatrix x4: lanes 0-15 -> rows 0-15 @k0, lanes 16-31 -> rows 0-15 @k0+8
// yields exactly (a0,a1,a2,a3) of mma.m16n8k16 A.
__device__ __forceinline__ void ldsm4(uint32_t& a0, uint32_t& a1, uint32_t& a2, uint32_t& a3,
                                      uint32_t addr) {
    asm volatile("ldmatrix.sync.aligned.m8n8.x4.shared.b16 {%0,%1,%2,%3}, [%4];"
                 : "=r"(a0), "=r"(a1), "=r"(a2), "=r"(a3) : "r"(addr));
}
__device__ __forceinline__ uint32_t packh2(float lo, float hi) {
    __half2 h = __floats2half2_rn(lo, hi);
    return *reinterpret_cast<uint32_t*>(&h);
}

// ---------------------------------------------------------------------------
// Prep: kernel[b,i,o,k,l] -> g_kth[b][l][k*1024 + f2]  (per-shift B-frag order)
// Also (block 0,0,0) packs conv_w -> g_w1h[k*512 + f1].
// ---------------------------------------------------------------------------
__global__ void prep_weights(const float* __restrict__ kin,
                             const float* __restrict__ conv_w) {
    __shared__ uint32_t tile[32][33];
    int b  = blockIdx.z;
    int f0 = blockIdx.x * 32;   // 96 blocks over f = 3072
    int l0 = blockIdx.y * 32;
    int tx = threadIdx.x, ty = threadIdx.y;
    const float* src = kin + (size_t)b * 6144 * 128;
    uint32_t*    dst = g_kth + (size_t)b * 128 * 3072;
#pragma unroll
    for (int r = 0; r < 4; r++) {
        int f = f0 + ty + r * 8;
        int k = f >> 10, f2 = f & 1023;
        int j = f2 & 3, lane = (f2 >> 2) & 31, blk = f2 >> 7;  // blk = ks*4+q
        int q = blk & 3, ks = blk >> 2;
        int tq = lane & 3, tr = lane >> 2;
        int nt = 2 * q + (j >> 1), reg = j & 1;
        int o  = nt * 8 + tr;
        int ci0 = ks * 16 + 2 * tq + 8 * reg;
        int mlo = ci0 * 192 + o * 3 + k;
        int mhi = (ci0 + 1) * 192 + o * 3 + k;
        tile[ty + r * 8][tx] = packh2(src[(size_t)mlo * 128 + l0 + tx],
                                      src[(size_t)mhi * 128 + l0 + tx]);
    }
    __syncthreads();
#pragma unroll
    for (int r = 0; r < 4; r++) {
        int l = l0 + ty + r * 8;
        dst[(size_t)l * 3072 + f0 + tx] = tile[tx][ty + r * 8];
    }
    if (blockIdx.x == 0 && blockIdx.y == 0 && blockIdx.z == 0) {
        int t = ty * 32 + tx;
        for (int f = t; f < 1536; f += 256) {
            int k = f >> 9, f1 = f & 511;
            int j = f1 & 3, lane = (f1 >> 2) & 31, blk = f1 >> 7;  // blk = ks*2+q
            int q = blk & 1, ks = blk >> 1;
            int tq = lane & 3, tr = lane >> 2;
            int nt = 2 * q + (j >> 1), reg = j & 1;
            int co = nt * 8 + tr;
            int ci0 = ks * 16 + 2 * tq + 8 * reg;
            g_w1h[f] = packh2(conv_w[co * 96 + 3 * ci0 + k],
                              conv_w[co * 96 + 3 * (ci0 + 1) + k]);
        }
    }
}

// ---------------------------------------------------------------------------
// Main fused kernel: one CTA per (256-position chunk, batch); 2 pipelined subs.
// ---------------------------------------------------------------------------
__global__ __launch_bounds__(256, 3)
void lvc_mma_kernel(const float* __restrict__ hidden,
                    const float* __restrict__ bias,
                    const float* __restrict__ conv_w,
                    const float* __restrict__ conv_b,
                    float* __restrict__ out) {
    extern __shared__ float sm[];
    uint32_t* w1u   = (uint32_t*)(sm + OF_W1);
    uint32_t* w2u   = (uint32_t*)(sm + OF_W2);
    float*    biasS = sm + OF_BIAS;
    float*    cbS   = sm + OF_CB;
    float*    hs0   = sm + OF_HS0;
    float*    hs1   = sm + OF_HS1;
    uint32_t* hTu   = (uint32_t*)(sm + OF_HT);
    uint32_t* xTu   = (uint32_t*)(sm + OF_XT);
    __half*   xTh   = (__half*)xTu;

    const int tid  = threadIdx.x;
    const int wid  = tid >> 5;
    const int lane = tid & 31;
    const int l    = blockIdx.x;
    const int b    = blockIdx.y;
    const float* hidB = hidden + (size_t)b * HID * LEN;
    const uint32_t hb0 = smem_u32p(hs0);
    const uint32_t hb1 = smem_u32p(hs1);

    // ---- prefetch sub0's hs tile (raw fp32) into buffer 0 ----
    {
        const int s0p = l * 256;
        for (int idx = tid; idx < 1088; idx += 256) {
            int c = idx / 34, gr = idx - c * 34;
            int g = s0p - 4 + gr * 4;
            bool in = (g >= 0) && (g + 4 <= LEN);
            const float* src = hidB + (size_t)c * LEN + (in ? g : 0);
            cp_async16(hb0 + (uint32_t)(c * HSS + gr * 4) * 4, src, in ? 16 : 0);
        }
        asm volatile("cp.async.commit_group;" ::: "memory");
    }

    // ---- stage weights; zero hT pad rows 136..151 ----
    {
        const uint4* w2s = (const uint4*)(g_kth + ((size_t)b * KLCH + l) * 3072);
        uint4* w2d = (uint4*)w2u;
        for (int i = tid; i < 768; i += 256) w2d[i] = w2s[i];
        const uint4* w1s = (const uint4*)g_w1h;
        uint4* w1d = (uint4*)w1u;
        for (int i = tid; i < 384; i += 256) w1d[i] = w1s[i];
        for (int i = tid; i < 320; i += 256) hTu[2720 + i] = 0;
    }
    if (tid < 64) biasS[tid] = bias[((size_t)b * 64 + tid) * KLCH + l];
    if (tid < 32) cbS[tid]   = conv_b[tid];

    const int tq = lane & 3;
    const int tr = lane >> 2;
    const int m0 = wid * 16;          // stage-1 m-tile
    const int mt2 = wid & 3;          // stage-2: 32-row block
    const int nh  = wid >> 2;         // stage-2: n-half (q parity)

    // ldmatrix lane base addresses (row = lane&15, col-u32 = (lane>>4)*4)
    const uint32_t hT_lane = smem_u32p(hTu) + (uint32_t)(((lane & 15) * TS + (lane >> 4) * 4) * 4);
    const uint32_t xT_lane = smem_u32p(xTu) + (uint32_t)(((lane & 15) * TS + (lane >> 4) * 4) * 4);

#pragma unroll
    for (int s = 0; s < 2; s++) {
        const int s0 = l * 256 + s * 128;
        float* hscur = s ? hs1 : hs0;

        asm volatile("cp.async.wait_group 0;" ::: "memory");
        __syncthreads();

        // issue next sub's prefetch immediately (into the other buffer)
        if (s == 0) {
            const int s0p = l * 256 + 128;
            for (int idx = tid; idx < 1088; idx += 256) {
                int c = idx / 34, gr = idx - c * 34;
                int g = s0p - 4 + gr * 4;
                bool in = (g >= 0) && (g + 4 <= LEN);
                const float* src = hidB + (size_t)c * LEN + (in ? g : 0);
                cp_async16(hb1 + (uint32_t)(c * HSS + gr * 4) * 4, src, in ? 16 : 0);
            }
            asm volatile("cp.async.commit_group;" ::: "memory");
        }

        // ---- P1: build hT (half2-pack transpose, low-conflict) ----
#pragma unroll
        for (int t = 0; t < 8; t++) {
            int g  = t * 8 + wid;           // 0..63
            int ce = (g & 3) * 4 + (lane >> 3);
            int v  = (g >> 2) * 8 + (lane & 7);
            float lo = leaky(hscur[(2 * ce)     * HSS + v]);
            float hi = leaky(hscur[(2 * ce + 1) * HSS + v]);
            hTu[v * TS + ce] = packh2(lo, hi);
        }
        if (tid < 128) {                    // tail v = 128..135
            int ce = tid >> 3, vr = tid & 7, v = 128 + vr;
            float lo = leaky(hscur[(2 * ce)     * HSS + v]);
            float hi = leaky(hscur[(2 * ce + 1) * HSS + v]);
            hTu[v * TS + ce] = packh2(lo, hi);
        }
        __syncthreads();

        // ---- P2: stage-1 shift-GEMM: 16m x 32n per warp, ldmatrix A ----
        float c1[4][4];
#pragma unroll
        for (int nt = 0; nt < 4; nt++)
#pragma unroll
            for (int j = 0; j < 4; j++) c1[nt][j] = 0.f;

        const uint4* w1q = (const uint4*)w1u;
#pragma unroll
        for (int k = 0; k < 3; k++) {
#pragma unroll
            for (int ks = 0; ks < 2; ks++) {
                uint32_t a0, a1, a2, a3;
                ldsm4(a0, a1, a2, a3, hT_lane + (uint32_t)(((m0 + 3 * k) * TS + ks * 8) * 4));
                uint4 q0 = w1q[k * 128 + ks * 64 + lane];
                uint4 q1 = w1q[k * 128 + ks * 64 + 32 + lane];
                mma_fp16(c1[0], a0, a1, a2, a3, q0.x, q0.y);
                mma_fp16(c1[1], a0, a1, a2, a3, q0.z, q0.w);
                mma_fp16(c1[2], a0, a1, a2, a3, q1.x, q1.y);
                mma_fp16(c1[3], a0, a1, a2, a3, q1.z, q1.w);
            }
        }

        // ---- P3: write xT[u][c] ----
#pragma unroll
        for (int nt = 0; nt < 4; nt++) {
#pragma unroll
            for (int j = 0; j < 4; j++) {
                int c = nt * 8 + 2 * tq + (j & 1);
                int u = m0 + tr + ((j >> 1) << 3);
                float v = leaky(c1[nt][j] + cbS[c]);
                xTh[u * 40 + c] = (s0 == 0 && u == 0) ? __half(0.f)
                                                      : __float2half_rn(v);
            }
        }
        // tail rows u = 128,129 via an extra MMA tile on warp 0
        if (wid == 0) {
            float c1b[4][4];
#pragma unroll
            for (int nt = 0; nt < 4; nt++)
#pragma unroll
                for (int j = 0; j < 4; j++) c1b[nt][j] = 0.f;
#pragma unroll
            for (int k = 0; k < 3; k++) {
#pragma unroll
                for (int ks = 0; ks < 2; ks++) {
                    uint32_t a0, a1, a2, a3;
                    ldsm4(a0, a1, a2, a3, hT_lane + (uint32_t)(((128 + 3 * k) * TS + ks * 8) * 4));
                    uint4 q0 = w1q[k * 128 + ks * 64 + lane];
                    uint4 q1 = w1q[k * 128 + ks * 64 + 32 + lane];
                    mma_fp16(c1b[0], a0, a1, a2, a3, q0.x, q0.y);
                    mma_fp16(c1b[1], a0, a1, a2, a3, q0.z, q0.w);
                    mma_fp16(c1b[2], a0, a1, a2, a3, q1.x, q1.y);
                    mma_fp16(c1b[3], a0, a1, a2, a3, q1.z, q1.w);
                }
            }
            if (tr < 2) {
                int u = 128 + tr;               // p = s0 + 127 + tr
                bool ok = (s0 + 127 + tr) < LEN;
#pragma unroll
                for (int nt = 0; nt < 4; nt++) {
#pragma unroll
                    for (int j = 0; j < 2; j++) {
                        int c = nt * 8 + 2 * tq + j;
                        float v = leaky(c1b[nt][j] + cbS[c]);
                        xTh[u * 40 + c] = ok ? __float2half_rn(v) : __half(0.f);
                    }
                }
            }
        }
        __syncthreads();

        // ---- P4: stage-2 shift-GEMM: 32m x 32n per warp (q-parity n-split) ----
        // warp (mt2, nh): rows 32*mt2..+31 ; n-tiles nt = {2nh, 2nh+1, 2nh+4, 2nh+5}
        float c2[2][4][4];
#pragma unroll
        for (int mt = 0; mt < 2; mt++)
#pragma unroll
            for (int ni = 0; ni < 4; ni++)
#pragma unroll
                for (int j = 0; j < 4; j++) c2[mt][ni][j] = 0.f;

        const uint4* w2q = (const uint4*)w2u;
#pragma unroll
        for (int k = 0; k < 3; k++) {
#pragma unroll
            for (int ks = 0; ks < 2; ks++) {
                uint4 qa = w2q[k * 256 + ks * 128 + nh * 32 + lane];        // nt 2nh, 2nh+1
                uint4 qb = w2q[k * 256 + ks * 128 + (nh + 2) * 32 + lane];  // nt 2nh+4, 2nh+5
#pragma unroll
                for (int mt = 0; mt < 2; mt++) {
                    uint32_t a0, a1, a2, a3;
                    ldsm4(a0, a1, a2, a3,
                          xT_lane + (uint32_t)(((mt2 * 32 + mt * 16 + k) * TS + ks * 8) * 4));
                    mma_fp16(c2[mt][0], a0, a1, a2, a3, qa.x, qa.y);
                    mma_fp16(c2[mt][1], a0, a1, a2, a3, qa.z, qa.w);
                    mma_fp16(c2[mt][2], a0, a1, a2, a3, qb.x, qb.y);
                    mma_fp16(c2[mt][3], a0, a1, a2, a3, qb.z, qb.w);
                }
            }
        }

        // ---- epilogue: gate + residual (pairs (o, o+32) within warp) ----
        {
            float* outB = out + (size_t)b * HID * LEN;
            const float LOG2E = 1.4426950408889634f;
#pragma unroll
            for (int mt = 0; mt < 2; mt++) {
#pragma unroll
                for (int ni = 0; ni < 2; ni++) {
                    int obase = (2 * nh + ni) * 8 + 2 * tq;
#pragma unroll
                    for (int j = 0; j < 4; j++) {
                        int oo = obase + (j & 1);
                        int m  = mt2 * 32 + mt * 16 + tr + ((j >> 1) << 3);
                        float gv = c2[mt][ni][j]     + biasS[oo];
                        float hv = c2[mt][ni + 2][j] + biasS[oo + 32];
                        float sig = fast_rcp(1.f + fast_ex2(-LOG2E * gv));
                        float res = hscur[oo * HSS + m + 4];
                        outB[(size_t)oo * LEN + s0 + m] = res + sig * fast_tanh(hv);
                    }
                }
            }
        }
    }
}

// ---------------------------------------------------------------------------
extern "C" void kernel_launch(void* const* d_in, const int* in_sizes, int n_in,
                              void* d_out, int out_size) {
    const float* hidden = (const float*)d_in[0];
    const float* kern   = (const float*)d_in[1];
    const float* bias   = (const float*)d_in[2];
    const float* conv_w = (const float*)d_in[3];
    const float* conv_b = (const float*)d_in[4];
    float* out = (float*)d_out;

    prep_weights<<<dim3(96, 4, 16), dim3(32, 8)>>>(kern, conv_w);

    int smem_bytes = SMEM_U32 * 4;   // 76,192 B
    cudaFuncSetAttribute(lvc_mma_kernel,
                         cudaFuncAttributeMaxDynamicSharedMemorySize, smem_bytes);
    lvc_mma_kernel<<<dim3(KLCH, BATCH), 256, smem_bytes>>>(hidden, bias, conv_w, conv_b, out);
}

// round 13
// speedup vs baseline: 2.2937x; 1.0225x over previous
#include <cuda_runtime.h>
#include <cuda_fp16.h>
#include <stdint.h>

#define HID   32
#define LEN   32768
#define BATCH 16
#define KLCH  128

#define HSS 136     // hs row stride (fp32 words)
#define TS  20      // hT/xT row stride in u32 (40 half)

// smem u32 offsets
#define OF_W1   0       // 1536 : conv W, per-shift frag order (half2)
#define OF_W2   1536    // 3072 : LVC W, per-shift frag order (half2)
#define OF_BIAS 4608    // 64 (fp32)
#define OF_CB   4672    // 32 (fp32)
#define OF_HS0  4704    // 4352 : raw fp32 hidden tile, buffer 0
#define OF_HS1  9056    // 4352 : buffer 1
#define OF_HT   13408   // 3040 : hT[152][40 half]; rows 136..151 zero
#define OF_XT   16448   // 2600 : xT[130][40 half]
#define SMEM_U32 19048  // 76,192 B -> 3 CTA/SM

// weights pre-packed per-shift (k=0..2), K=32, m16n8k16 B-frag order, half2-in-u32
__device__ __align__(16) uint32_t g_kth[(size_t)BATCH * KLCH * 3072];  // 25 MB
__device__ __align__(16) uint32_t g_w1h[1536];

__device__ __forceinline__ float fast_tanh(float x) { float r; asm("tanh.approx.f32 %0, %1;" : "=f"(r) : "f"(x)); return r; }
__device__ __forceinline__ float fast_ex2(float x)  { float r; asm("ex2.approx.f32 %0, %1;"  : "=f"(r) : "f"(x)); return r; }
__device__ __forceinline__ float fast_rcp(float x)  { float r; asm("rcp.approx.f32 %0, %1;"  : "=f"(r) : "f"(x)); return r; }
__device__ __forceinline__ float leaky(float x) { return (x >= 0.f) ? x : 0.2f * x; }

__device__ __forceinline__ uint32_t smem_u32p(const void* p) {
    uint32_t a; asm("{ .reg .u64 t; cvta.to.shared.u64 t, %1; cvt.u32.u64 %0, t; }" : "=r"(a) : "l"(p));
    return a;
}
__device__ __forceinline__ void cp_async16(uint32_t dst, const void* src, int src_bytes) {
    asm volatile("cp.async.ca.shared.global [%0], [%1], 16, %2;"
                 :: "r"(dst), "l"(src), "r"(src_bytes) : "memory");
}
__device__ __forceinline__ void mma_fp16(float c[4],
                                         uint32_t a0, uint32_t a1, uint32_t a2, uint32_t a3,
                                         uint32_t b0, uint32_t b1) {
    asm volatile(
        "mma.sync.aligned.m16n8k16.row.col.f32.f16.f16.f32 "
        "{%0,%1,%2,%3}, {%4,%5,%6,%7}, {%8,%9}, {%0,%1,%2,%3};"
        : "+f"(c[0]), "+f"(c[1]), "+f"(c[2]), "+f"(c[3])
        : "r"(a0), "r"(a1), "r"(a2), "r"(a3), "r"(b0), "r"(b1));
}
__device__ __forceinline__ void ldsm4(uint32_t& a0, uint32_t& a1, uint32_t& a2, uint32_t& a3,
                                      uint32_t addr) {
    asm volatile("ldmatrix.sync.aligned.m8n8.x4.shared.b16 {%0,%1,%2,%3}, [%4];"
                 : "=r"(a0), "=r"(a1), "=r"(a2), "=r"(a3) : "r"(addr));
}
__device__ __forceinline__ uint32_t packh2(float lo, float hi) {
    __half2 h = __floats2half2_rn(lo, hi);
    return *reinterpret_cast<uint32_t*>(&h);
}

// ---------------------------------------------------------------------------
// Prep: kernel[b,i,o,k,l] -> g_kth[b][l][k*1024 + f2]  (per-shift B-frag order)
// Also (block 0,0,0) packs conv_w -> g_w1h[k*512 + f1].
// ---------------------------------------------------------------------------
__global__ void prep_weights(const float* __restrict__ kin,
                             const float* __restrict__ conv_w) {
    __shared__ uint32_t tile[32][33];
    int b  = blockIdx.z;
    int f0 = blockIdx.x * 32;
    int l0 = blockIdx.y * 32;
    int tx = threadIdx.x, ty = threadIdx.y;
    const float* src = kin + (size_t)b * 6144 * 128;
    uint32_t*    dst = g_kth + (size_t)b * 128 * 3072;
#pragma unroll
    for (int r = 0; r < 4; r++) {
        int f = f0 + ty + r * 8;
        int k = f >> 10, f2 = f & 1023;
        int j = f2 & 3, lane = (f2 >> 2) & 31, blk = f2 >> 7;  // blk = ks*4+q
        int q = blk & 3, ks = blk >> 2;
        int tq = lane & 3, tr = lane >> 2;
        int nt = 2 * q + (j >> 1), reg = j & 1;
        int o  = nt * 8 + tr;
        int ci0 = ks * 16 + 2 * tq + 8 * reg;
        int mlo = ci0 * 192 + o * 3 + k;
        int mhi = (ci0 + 1) * 192 + o * 3 + k;
        tile[ty + r * 8][tx] = packh2(src[(size_t)mlo * 128 + l0 + tx],
                                      src[(size_t)mhi * 128 + l0 + tx]);
    }
    __syncthreads();
#pragma unroll
    for (int r = 0; r < 4; r++) {
        int l = l0 + ty + r * 8;
        dst[(size_t)l * 3072 + f0 + tx] = tile[tx][ty + r * 8];
    }
    if (blockIdx.x == 0 && blockIdx.y == 0 && blockIdx.z == 0) {
        int t = ty * 32 + tx;
        for (int f = t; f < 1536; f += 256) {
            int k = f >> 9, f1 = f & 511;
            int j = f1 & 3, lane = (f1 >> 2) & 31, blk = f1 >> 7;  // blk = ks*2+q
            int q = blk & 1, ks = blk >> 1;
            int tq = lane & 3, tr = lane >> 2;
            int nt = 2 * q + (j >> 1), reg = j & 1;
            int co = nt * 8 + tr;
            int ci0 = ks * 16 + 2 * tq + 8 * reg;
            g_w1h[f] = packh2(conv_w[co * 96 + 3 * ci0 + k],
                              conv_w[co * 96 + 3 * (ci0 + 1) + k]);
        }
    }
}

// ---------------------------------------------------------------------------
// Main fused kernel: one CTA per (256-position chunk, batch); 2 pipelined subs.
// ---------------------------------------------------------------------------
__global__ __launch_bounds__(256, 3)
void lvc_mma_kernel(const float* __restrict__ hidden,
                    const float* __restrict__ bias,
                    const float* __restrict__ conv_w,
                    const float* __restrict__ conv_b,
                    float* __restrict__ out) {
    extern __shared__ float sm[];
    uint32_t* w1u   = (uint32_t*)(sm + OF_W1);
    uint32_t* w2u   = (uint32_t*)(sm + OF_W2);
    float*    biasS = sm + OF_BIAS;
    float*    cbS   = sm + OF_CB;
    float*    hs0   = sm + OF_HS0;
    float*    hs1   = sm + OF_HS1;
    uint32_t* hTu   = (uint32_t*)(sm + OF_HT);
    uint32_t* xTu   = (uint32_t*)(sm + OF_XT);

    const int tid  = threadIdx.x;
    const int wid  = tid >> 5;
    const int lane = tid & 31;
    const int l    = blockIdx.x;
    const int b    = blockIdx.y;
    const float* hidB = hidden + (size_t)b * HID * LEN;
    const uint32_t hb0 = smem_u32p(hs0);
    const uint32_t hb1 = smem_u32p(hs1);

    // ---- prefetch sub0's hs tile (raw fp32) into buffer 0 ----
    {
        const int s0p = l * 256;
        for (int idx = tid; idx < 1088; idx += 256) {
            int c = idx / 34, gr = idx - c * 34;
            int g = s0p - 4 + gr * 4;
            bool in = (g >= 0) && (g + 4 <= LEN);
            const float* src = hidB + (size_t)c * LEN + (in ? g : 0);
            cp_async16(hb0 + (uint32_t)(c * HSS + gr * 4) * 4, src, in ? 16 : 0);
        }
        asm volatile("cp.async.commit_group;" ::: "memory");
    }

    // ---- stage weights; zero hT pad rows 136..151 ----
    {
        const uint4* w2s = (const uint4*)(g_kth + ((size_t)b * KLCH + l) * 3072);
        uint4* w2d = (uint4*)w2u;
        for (int i = tid; i < 768; i += 256) w2d[i] = w2s[i];
        const uint4* w1s = (const uint4*)g_w1h;
        uint4* w1d = (uint4*)w1u;
        for (int i = tid; i < 384; i += 256) w1d[i] = w1s[i];
        for (int i = tid; i < 320; i += 256) hTu[2720 + i] = 0;
    }
    if (tid < 64) biasS[tid] = bias[((size_t)b * 64 + tid) * KLCH + l];
    if (tid < 32) cbS[tid]   = conv_b[tid];

    const int tq = lane & 3;
    const int tr = lane >> 2;
    const int m0 = wid * 16;          // stage-1 m-tile
    const int mt2 = wid & 3;          // stage-2: 32-row block
    const int nh  = wid >> 2;         // stage-2: n-half (q parity)

    // P1 diagonal transpose mapping (conflict-free loads AND stores)
    const int ceP = tid & 15;
    const int g2P = tid >> 4;

    // ldmatrix lane base addresses (row = lane&15, col-u32 = (lane>>4)*4)
    const uint32_t hT_lane = smem_u32p(hTu) + (uint32_t)(((lane & 15) * TS + (lane >> 4) * 4) * 4);
    const uint32_t xT_lane = smem_u32p(xTu) + (uint32_t)(((lane & 15) * TS + (lane >> 4) * 4) * 4);

#pragma unroll
    for (int s = 0; s < 2; s++) {
        const int s0 = l * 256 + s * 128;
        float* hscur = s ? hs1 : hs0;

        asm volatile("cp.async.wait_group 0;" ::: "memory");
        __syncthreads();

        // issue next sub's prefetch immediately (into the other buffer)
        if (s == 0) {
            const int s0p = l * 256 + 128;
            for (int idx = tid; idx < 1088; idx += 256) {
                int c = idx / 34, gr = idx - c * 34;
                int g = s0p - 4 + gr * 4;
                bool in = (g >= 0) && (g + 4 <= LEN);
                const float* src = hidB + (size_t)c * LEN + (in ? g : 0);
                cp_async16(hb1 + (uint32_t)(c * HSS + gr * 4) * 4, src, in ? 16 : 0);
            }
            asm volatile("cp.async.commit_group;" ::: "memory");
        }

        // ---- P1: build hT — diagonal float2 transpose, conflict-free ----
        // word hT[v][ce] = (leaky(hs[2ce][v]), leaky(hs[2ce+1][v])); v = 2vp, 2vp+1
#pragma unroll
        for (int it = 0; it < 5; it++) {
            int vp = it * 16 + g2P + ceP;
            if (vp >= 80) vp -= 80;
            if (vp < 68) {
                float2 lo2 = *(const float2*)(hscur + (2 * ceP)     * HSS + 2 * vp);
                float2 hi2 = *(const float2*)(hscur + (2 * ceP + 1) * HSS + 2 * vp);
                hTu[(2 * vp)     * TS + ceP] = packh2(leaky(lo2.x), leaky(hi2.x));
                hTu[(2 * vp + 1) * TS + ceP] = packh2(leaky(lo2.y), leaky(hi2.y));
            }
        }
        __syncthreads();

        // ---- P2: stage-1 shift-GEMM: 16m x 32n per warp, ldmatrix A ----
        float c1[4][4];
#pragma unroll
        for (int nt = 0; nt < 4; nt++)
#pragma unroll
            for (int j = 0; j < 4; j++) c1[nt][j] = 0.f;

        const uint4* w1q = (const uint4*)w1u;
#pragma unroll
        for (int k = 0; k < 3; k++) {
#pragma unroll
            for (int ks = 0; ks < 2; ks++) {
                uint32_t a0, a1, a2, a3;
                ldsm4(a0, a1, a2, a3, hT_lane + (uint32_t)(((m0 + 3 * k) * TS + ks * 8) * 4));
                uint4 q0 = w1q[k * 128 + ks * 64 + lane];
                uint4 q1 = w1q[k * 128 + ks * 64 + 32 + lane];
                mma_fp16(c1[0], a0, a1, a2, a3, q0.x, q0.y);
                mma_fp16(c1[1], a0, a1, a2, a3, q0.z, q0.w);
                mma_fp16(c1[2], a0, a1, a2, a3, q1.x, q1.y);
                mma_fp16(c1[3], a0, a1, a2, a3, q1.z, q1.w);
            }
        }

        // ---- P3: write xT — paired u32 stores, conflict-free ----
        {
            const int u = m0 + tr;
            const bool z0 = (s0 == 0) && (u == 0);
#pragma unroll
            for (int nt = 0; nt < 4; nt++) {
                int c  = nt * 8 + 2 * tq;
                int cw = nt * 4 + tq;
                float bA = cbS[c], bB = cbS[c + 1];
                uint32_t wlo = packh2(leaky(c1[nt][0] + bA), leaky(c1[nt][1] + bB));
                uint32_t whi = packh2(leaky(c1[nt][2] + bA), leaky(c1[nt][3] + bB));
                xTu[u * TS + cw]       = z0 ? 0u : wlo;
                xTu[(u + 8) * TS + cw] = whi;
            }
        }
        // tail rows u = 128,129 via an extra MMA tile on warp 0
        if (wid == 0) {
            float c1b[4][4];
#pragma unroll
            for (int nt = 0; nt < 4; nt++)
#pragma unroll
                for (int j = 0; j < 4; j++) c1b[nt][j] = 0.f;
#pragma unroll
            for (int k = 0; k < 3; k++) {
#pragma unroll
                for (int ks = 0; ks < 2; ks++) {
                    uint32_t a0, a1, a2, a3;
                    ldsm4(a0, a1, a2, a3, hT_lane + (uint32_t)(((128 + 3 * k) * TS + ks * 8) * 4));
                    uint4 q0 = w1q[k * 128 + ks * 64 + lane];
                    uint4 q1 = w1q[k * 128 + ks * 64 + 32 + lane];
                    mma_fp16(c1b[0], a0, a1, a2, a3, q0.x, q0.y);
                    mma_fp16(c1b[1], a0, a1, a2, a3, q0.z, q0.w);
                    mma_fp16(c1b[2], a0, a1, a2, a3, q1.x, q1.y);
                    mma_fp16(c1b[3], a0, a1, a2, a3, q1.z, q1.w);
                }
            }
            if (tr < 2) {
                int u = 128 + tr;               // p = s0 + 127 + tr
                bool ok = (s0 + 127 + tr) < LEN;
#pragma unroll
                for (int nt = 0; nt < 4; nt++) {
                    int c  = nt * 8 + 2 * tq;
                    uint32_t w = packh2(leaky(c1b[nt][0] + cbS[c]),
                                        leaky(c1b[nt][1] + cbS[c + 1]));
                    xTu[u * TS + nt * 4 + tq] = ok ? w : 0u;
                }
            }
        }
        __syncthreads();

        // ---- P4: stage-2 shift-GEMM: 32m x 32n per warp (q-parity n-split) ----
        float c2[2][4][4];
#pragma unroll
        for (int mt = 0; mt < 2; mt++)
#pragma unroll
            for (int ni = 0; ni < 4; ni++)
#pragma unroll
                for (int j = 0; j < 4; j++) c2[mt][ni][j] = 0.f;

        const uint4* w2q = (const uint4*)w2u;
#pragma unroll
        for (int k = 0; k < 3; k++) {
#pragma unroll
            for (int ks = 0; ks < 2; ks++) {
                uint4 qa = w2q[k * 256 + ks * 128 + nh * 32 + lane];        // nt 2nh, 2nh+1
                uint4 qb = w2q[k * 256 + ks * 128 + (nh + 2) * 32 + lane];  // nt 2nh+4, 2nh+5
#pragma unroll
                for (int mt = 0; mt < 2; mt++) {
                    uint32_t a0, a1, a2, a3;
                    ldsm4(a0, a1, a2, a3,
                          xT_lane + (uint32_t)(((mt2 * 32 + mt * 16 + k) * TS + ks * 8) * 4));
                    mma_fp16(c2[mt][0], a0, a1, a2, a3, qa.x, qa.y);
                    mma_fp16(c2[mt][1], a0, a1, a2, a3, qa.z, qa.w);
                    mma_fp16(c2[mt][2], a0, a1, a2, a3, qb.x, qb.y);
                    mma_fp16(c2[mt][3], a0, a1, a2, a3, qb.z, qb.w);
                }
            }
        }

        // ---- epilogue: gate + residual (pairs (o, o+32) within warp) ----
        {
            float* outB = out + (size_t)b * HID * LEN;
            const float LOG2E = 1.4426950408889634f;
#pragma unroll
            for (int mt = 0; mt < 2; mt++) {
#pragma unroll
                for (int ni = 0; ni < 2; ni++) {
                    int obase = (2 * nh + ni) * 8 + 2 * tq;
#pragma unroll
                    for (int j = 0; j < 4; j++) {
                        int oo = obase + (j & 1);
                        int m  = mt2 * 32 + mt * 16 + tr + ((j >> 1) << 3);
                        float gv = c2[mt][ni][j]     + biasS[oo];
                        float hv = c2[mt][ni + 2][j] + biasS[oo + 32];
                        float sig = fast_rcp(1.f + fast_ex2(-LOG2E * gv));
                        float res = hscur[oo * HSS + m + 4];
                        outB[(size_t)oo * LEN + s0 + m] = res + sig * fast_tanh(hv);
                    }
                }
            }
        }
    }
}

// ---------------------------------------------------------------------------
extern "C" void kernel_launch(void* const* d_in, const int* in_sizes, int n_in,
                              void* d_out, int out_size) {
    const float* hidden = (const float*)d_in[0];
    const float* kern   = (const float*)d_in[1];
    const float* bias   = (const float*)d_in[2];
    const float* conv_w = (const float*)d_in[3];
    const float* conv_b = (const float*)d_in[4];
    float* out = (float*)d_out;

    prep_weights<<<dim3(96, 4, 16), dim3(32, 8)>>>(kern, conv_w);

    int smem_bytes = SMEM_U32 * 4;   // 76,192 B
    cudaFuncSetAttribute(lvc_mma_kernel,
                         cudaFuncAttributeMaxDynamicSharedMemorySize, smem_bytes);
    lvc_mma_kernel<<<dim3(KLCH, BATCH), 256, smem_bytes>>>(hidden, bias, conv_w, conv_b, out);
}

// round 14
// speedup vs baseline: 2.4188x; 1.0545x over previous
#include <cuda_runtime.h>
#include <cuda_fp16.h>
#include <stdint.h>

#define HID   32
#define LEN   32768
#define BATCH 16
#define KLCH  128

#define HSS 136     // hs row stride (fp32 words)
#define TS  20      // hT/xT row stride in u32 (40 half)

// smem u32 offsets
#define OF_W2   0       // 3072 : LVC W, per-shift frag order (half2)
#define OF_BIAS 3072    // 64 (fp32)
#define OF_CB   3136    // 32 (fp32)
#define OF_HS   3168    // 4352 : raw fp32 hidden tile (single buffer)
#define OF_HT   7520    // 3040 : hT[152][40 half]; rows 136..151 zero
#define OF_XT   10560   // 2600 : xT[130][40 half]
#define SMEM_U32 13160  // 52,640 B -> 4 CTA/SM

// weights pre-packed per-shift (k=0..2), K=32, m16n8k16 B-frag order, half2-in-u32
__device__ __align__(16) uint32_t g_kth[(size_t)BATCH * KLCH * 3072];  // 25 MB
__device__ __align__(16) uint32_t g_w1h[1536];

__device__ __forceinline__ float fast_tanh(float x) { float r; asm("tanh.approx.f32 %0, %1;" : "=f"(r) : "f"(x)); return r; }
__device__ __forceinline__ float fast_ex2(float x)  { float r; asm("ex2.approx.f32 %0, %1;"  : "=f"(r) : "f"(x)); return r; }
__device__ __forceinline__ float fast_rcp(float x)  { float r; asm("rcp.approx.f32 %0, %1;"  : "=f"(r) : "f"(x)); return r; }
__device__ __forceinline__ float leaky(float x) { return (x >= 0.f) ? x : 0.2f * x; }

__device__ __forceinline__ uint32_t smem_u32p(const void* p) {
    uint32_t a; asm("{ .reg .u64 t; cvta.to.shared.u64 t, %1; cvt.u32.u64 %0, t; }" : "=r"(a) : "l"(p));
    return a;
}
__device__ __forceinline__ void cp_async16(uint32_t dst, const void* src, int src_bytes) {
    asm volatile("cp.async.ca.shared.global [%0], [%1], 16, %2;"
                 :: "r"(dst), "l"(src), "r"(src_bytes) : "memory");
}
__device__ __forceinline__ void mma_fp16(float c[4],
                                         uint32_t a0, uint32_t a1, uint32_t a2, uint32_t a3,
                                         uint32_t b0, uint32_t b1) {
    asm volatile(
        "mma.sync.aligned.m16n8k16.row.col.f32.f16.f16.f32 "
        "{%0,%1,%2,%3}, {%4,%5,%6,%7}, {%8,%9}, {%0,%1,%2,%3};"
        : "+f"(c[0]), "+f"(c[1]), "+f"(c[2]), "+f"(c[3])
        : "r"(a0), "r"(a1), "r"(a2), "r"(a3), "r"(b0), "r"(b1));
}
__device__ __forceinline__ void ldsm4(uint32_t& a0, uint32_t& a1, uint32_t& a2, uint32_t& a3,
                                      uint32_t addr) {
    asm volatile("ldmatrix.sync.aligned.m8n8.x4.shared.b16 {%0,%1,%2,%3}, [%4];"
                 : "=r"(a0), "=r"(a1), "=r"(a2), "=r"(a3) : "r"(addr));
}
__device__ __forceinline__ uint32_t packh2(float lo, float hi) {
    __half2 h = __floats2half2_rn(lo, hi);
    return *reinterpret_cast<uint32_t*>(&h);
}

// ---------------------------------------------------------------------------
// Prep: kernel[b,i,o,k,l] -> g_kth[b][l][k*1024 + f2]  (per-shift B-frag order)
// Also (block 0,0,0) packs conv_w -> g_w1h[k*512 + f1].
// ---------------------------------------------------------------------------
__global__ void prep_weights(const float* __restrict__ kin,
                             const float* __restrict__ conv_w) {
    __shared__ uint32_t tile[32][33];
    int b  = blockIdx.z;
    int f0 = blockIdx.x * 32;
    int l0 = blockIdx.y * 32;
    int tx = threadIdx.x, ty = threadIdx.y;
    const float* src = kin + (size_t)b * 6144 * 128;
    uint32_t*    dst = g_kth + (size_t)b * 128 * 3072;
#pragma unroll
    for (int r = 0; r < 4; r++) {
        int f = f0 + ty + r * 8;
        int k = f >> 10, f2 = f & 1023;
        int j = f2 & 3, lane = (f2 >> 2) & 31, blk = f2 >> 7;  // blk = ks*4+q
        int q = blk & 3, ks = blk >> 2;
        int tq = lane & 3, tr = lane >> 2;
        int nt = 2 * q + (j >> 1), reg = j & 1;
        int o  = nt * 8 + tr;
        int ci0 = ks * 16 + 2 * tq + 8 * reg;
        int mlo = ci0 * 192 + o * 3 + k;
        int mhi = (ci0 + 1) * 192 + o * 3 + k;
        tile[ty + r * 8][tx] = packh2(src[(size_t)mlo * 128 + l0 + tx],
                                      src[(size_t)mhi * 128 + l0 + tx]);
    }
    __syncthreads();
#pragma unroll
    for (int r = 0; r < 4; r++) {
        int l = l0 + ty + r * 8;
        dst[(size_t)l * 3072 + f0 + tx] = tile[tx][ty + r * 8];
    }
    if (blockIdx.x == 0 && blockIdx.y == 0 && blockIdx.z == 0) {
        int t = ty * 32 + tx;
        for (int f = t; f < 1536; f += 256) {
            int k = f >> 9, f1 = f & 511;
            int j = f1 & 3, lane = (f1 >> 2) & 31, blk = f1 >> 7;  // blk = ks*2+q
            int q = blk & 1, ks = blk >> 1;
            int tq = lane & 3, tr = lane >> 2;
            int nt = 2 * q + (j >> 1), reg = j & 1;
            int co = nt * 8 + tr;
            int ci0 = ks * 16 + 2 * tq + 8 * reg;
            g_w1h[f] = packh2(conv_w[co * 96 + 3 * ci0 + k],
                              conv_w[co * 96 + 3 * (ci0 + 1) + k]);
        }
    }
}

// ---------------------------------------------------------------------------
// Main fused kernel: one CTA per (256-position chunk, batch); 2 pipelined subs.
// Slim-smem variant: single hs buffer, residual via inverse-leaky from hT,
// stage-1 weights loaded from global. 4 CTA/SM.
// ---------------------------------------------------------------------------
__global__ __launch_bounds__(256, 4)
void lvc_mma_kernel(const float* __restrict__ hidden,
                    const float* __restrict__ bias,
                    const float* __restrict__ conv_w,
                    const float* __restrict__ conv_b,
                    float* __restrict__ out) {
    extern __shared__ float sm[];
    uint32_t* w2u   = (uint32_t*)(sm + OF_W2);
    float*    biasS = sm + OF_BIAS;
    float*    cbS   = sm + OF_CB;
    float*    hsf   = sm + OF_HS;
    uint32_t* hTu   = (uint32_t*)(sm + OF_HT);
    uint32_t* xTu   = (uint32_t*)(sm + OF_XT);
    const __half* hTh = (const __half*)hTu;

    const int tid  = threadIdx.x;
    const int wid  = tid >> 5;
    const int lane = tid & 31;
    const int l    = blockIdx.x;
    const int b    = blockIdx.y;
    const float* hidB = hidden + (size_t)b * HID * LEN;
    const uint32_t hb = smem_u32p(hsf);

    // ---- prefetch sub0's hs tile (raw fp32) ----
    {
        const int s0p = l * 256;
        for (int idx = tid; idx < 1088; idx += 256) {
            int c = idx / 34, gr = idx - c * 34;
            int g = s0p - 4 + gr * 4;
            bool in = (g >= 0) && (g + 4 <= LEN);
            const float* src = hidB + (size_t)c * LEN + (in ? g : 0);
            cp_async16(hb + (uint32_t)(c * HSS + gr * 4) * 4, src, in ? 16 : 0);
        }
        asm volatile("cp.async.commit_group;" ::: "memory");
    }

    // ---- stage w2; zero hT pad rows 136..151 ----
    {
        const uint4* w2s = (const uint4*)(g_kth + ((size_t)b * KLCH + l) * 3072);
        uint4* w2d = (uint4*)w2u;
        for (int i = tid; i < 768; i += 256) w2d[i] = w2s[i];
        for (int i = tid; i < 320; i += 256) hTu[2720 + i] = 0;
    }
    if (tid < 64) biasS[tid] = bias[((size_t)b * 64 + tid) * KLCH + l];
    if (tid < 32) cbS[tid]   = conv_b[tid];

    const int tq = lane & 3;
    const int tr = lane >> 2;
    const int m0 = wid * 16;          // stage-1 m-tile
    const int mt2 = wid & 3;          // stage-2: 32-row block
    const int nh  = wid >> 2;         // stage-2: n-half (q parity)

    // P1 diagonal transpose mapping (conflict-free loads AND stores)
    const int ceP = tid & 15;
    const int g2P = tid >> 4;

    // ldmatrix lane base addresses (row = lane&15, col-u32 = (lane>>4)*4)
    const uint32_t hT_lane = smem_u32p(hTu) + (uint32_t)(((lane & 15) * TS + (lane >> 4) * 4) * 4);
    const uint32_t xT_lane = smem_u32p(xTu) + (uint32_t)(((lane & 15) * TS + (lane >> 4) * 4) * 4);

    const uint4* w1g = (const uint4*)g_w1h;   // stage-1 B from global (L1-resident)

#pragma unroll
    for (int s = 0; s < 2; s++) {
        const int s0 = l * 256 + s * 128;

        asm volatile("cp.async.wait_group 0;" ::: "memory");
        __syncthreads();   // hs ready; also orders prev-sub hT readers before P1 writes

        // ---- P1: build hT — diagonal float2 transpose, conflict-free ----
#pragma unroll
        for (int it = 0; it < 5; it++) {
            int vp = it * 16 + g2P + ceP;
            if (vp >= 80) vp -= 80;
            if (vp < 68) {
                float2 lo2 = *(const float2*)(hsf + (2 * ceP)     * HSS + 2 * vp);
                float2 hi2 = *(const float2*)(hsf + (2 * ceP + 1) * HSS + 2 * vp);
                hTu[(2 * vp)     * TS + ceP] = packh2(leaky(lo2.x), leaky(hi2.x));
                hTu[(2 * vp + 1) * TS + ceP] = packh2(leaky(lo2.y), leaky(hi2.y));
            }
        }
        __syncthreads();   // hT complete AND hs reads complete

        // hs is dead: prefetch next sub's tile into the same buffer
        if (s == 0) {
            const int s0p = l * 256 + 128;
            for (int idx = tid; idx < 1088; idx += 256) {
                int c = idx / 34, gr = idx - c * 34;
                int g = s0p - 4 + gr * 4;
                bool in = (g >= 0) && (g + 4 <= LEN);
                const float* src = hidB + (size_t)c * LEN + (in ? g : 0);
                cp_async16(hb + (uint32_t)(c * HSS + gr * 4) * 4, src, in ? 16 : 0);
            }
            asm volatile("cp.async.commit_group;" ::: "memory");
        }

        // ---- P2: stage-1 shift-GEMM: 16m x 32n per warp, ldmatrix A ----
        float c1[4][4];
#pragma unroll
        for (int nt = 0; nt < 4; nt++)
#pragma unroll
            for (int j = 0; j < 4; j++) c1[nt][j] = 0.f;

#pragma unroll
        for (int k = 0; k < 3; k++) {
#pragma unroll
            for (int ks = 0; ks < 2; ks++) {
                uint32_t a0, a1, a2, a3;
                ldsm4(a0, a1, a2, a3, hT_lane + (uint32_t)(((m0 + 3 * k) * TS + ks * 8) * 4));
                uint4 q0 = w1g[k * 128 + ks * 64 + lane];
                uint4 q1 = w1g[k * 128 + ks * 64 + 32 + lane];
                mma_fp16(c1[0], a0, a1, a2, a3, q0.x, q0.y);
                mma_fp16(c1[1], a0, a1, a2, a3, q0.z, q0.w);
                mma_fp16(c1[2], a0, a1, a2, a3, q1.x, q1.y);
                mma_fp16(c1[3], a0, a1, a2, a3, q1.z, q1.w);
            }
        }

        // ---- P3: write xT — paired u32 stores, conflict-free ----
        {
            const int u = m0 + tr;
            const bool z0 = (s0 == 0) && (u == 0);
#pragma unroll
            for (int nt = 0; nt < 4; nt++) {
                int c  = nt * 8 + 2 * tq;
                int cw = nt * 4 + tq;
                float bA = cbS[c], bB = cbS[c + 1];
                uint32_t wlo = packh2(leaky(c1[nt][0] + bA), leaky(c1[nt][1] + bB));
                uint32_t whi = packh2(leaky(c1[nt][2] + bA), leaky(c1[nt][3] + bB));
                xTu[u * TS + cw]       = z0 ? 0u : wlo;
                xTu[(u + 8) * TS + cw] = whi;
            }
        }
        // tail rows u = 128,129 via an extra MMA tile on warp 0
        if (wid == 0) {
            float c1b[4][4];
#pragma unroll
            for (int nt = 0; nt < 4; nt++)
#pragma unroll
                for (int j = 0; j < 4; j++) c1b[nt][j] = 0.f;
#pragma unroll
            for (int k = 0; k < 3; k++) {
#pragma unroll
                for (int ks = 0; ks < 2; ks++) {
                    uint32_t a0, a1, a2, a3;
                    ldsm4(a0, a1, a2, a3, hT_lane + (uint32_t)(((128 + 3 * k) * TS + ks * 8) * 4));
                    uint4 q0 = w1g[k * 128 + ks * 64 + lane];
                    uint4 q1 = w1g[k * 128 + ks * 64 + 32 + lane];
                    mma_fp16(c1b[0], a0, a1, a2, a3, q0.x, q0.y);
                    mma_fp16(c1b[1], a0, a1, a2, a3, q0.z, q0.w);
                    mma_fp16(c1b[2], a0, a1, a2, a3, q1.x, q1.y);
                    mma_fp16(c1b[3], a0, a1, a2, a3, q1.z, q1.w);
                }
            }
            if (tr < 2) {
                int u = 128 + tr;               // p = s0 + 127 + tr
                bool ok = (s0 + 127 + tr) < LEN;
#pragma unroll
                for (int nt = 0; nt < 4; nt++) {
                    int c  = nt * 8 + 2 * tq;
                    uint32_t w = packh2(leaky(c1b[nt][0] + cbS[c]),
                                        leaky(c1b[nt][1] + cbS[c + 1]));
                    xTu[u * TS + nt * 4 + tq] = ok ? w : 0u;
                }
            }
        }
        __syncthreads();

        // ---- P4: stage-2 shift-GEMM: 32m x 32n per warp (q-parity n-split) ----
        float c2[2][4][4];
#pragma unroll
        for (int mt = 0; mt < 2; mt++)
#pragma unroll
            for (int ni = 0; ni < 4; ni++)
#pragma unroll
                for (int j = 0; j < 4; j++) c2[mt][ni][j] = 0.f;

        const uint4* w2q = (const uint4*)w2u;
#pragma unroll
        for (int k = 0; k < 3; k++) {
#pragma unroll
            for (int ks = 0; ks < 2; ks++) {
                uint4 qa = w2q[k * 256 + ks * 128 + nh * 32 + lane];        // nt 2nh, 2nh+1
                uint4 qb = w2q[k * 256 + ks * 128 + (nh + 2) * 32 + lane];  // nt 2nh+4, 2nh+5
#pragma unroll
                for (int mt = 0; mt < 2; mt++) {
                    uint32_t a0, a1, a2, a3;
                    ldsm4(a0, a1, a2, a3,
                          xT_lane + (uint32_t)(((mt2 * 32 + mt * 16 + k) * TS + ks * 8) * 4));
                    mma_fp16(c2[mt][0], a0, a1, a2, a3, qa.x, qa.y);
                    mma_fp16(c2[mt][1], a0, a1, a2, a3, qa.z, qa.w);
                    mma_fp16(c2[mt][2], a0, a1, a2, a3, qb.x, qb.y);
                    mma_fp16(c2[mt][3], a0, a1, a2, a3, qb.z, qb.w);
                }
            }
        }

        // ---- epilogue: gate + residual (residual = inverse-leaky of hT) ----
        {
            float* outB = out + (size_t)b * HID * LEN;
            const float LOG2E = 1.4426950408889634f;
#pragma unroll
            for (int mt = 0; mt < 2; mt++) {
#pragma unroll
                for (int ni = 0; ni < 2; ni++) {
                    int obase = (2 * nh + ni) * 8 + 2 * tq;
#pragma unroll
                    for (int j = 0; j < 4; j++) {
                        int oo = obase + (j & 1);
                        int m  = mt2 * 32 + mt * 16 + tr + ((j >> 1) << 3);
                        float gv = c2[mt][ni][j]     + biasS[oo];
                        float hv = c2[mt][ni + 2][j] + biasS[oo + 32];
                        float sig = fast_rcp(1.f + fast_ex2(-LOG2E * gv));
                        float ry = __half2float(hTh[(m + 4) * 40 + oo]);
                        float res = (ry >= 0.f) ? ry : 5.f * ry;
                        outB[(size_t)oo * LEN + s0 + m] = res + sig * fast_tanh(hv);
                    }
                }
            }
        }
    }
}

// ---------------------------------------------------------------------------
extern "C" void kernel_launch(void* const* d_in, const int* in_sizes, int n_in,
                              void* d_out, int out_size) {
    const float* hidden = (const float*)d_in[0];
    const float* kern   = (const float*)d_in[1];
    const float* bias   = (const float*)d_in[2];
    const float* conv_w = (const float*)d_in[3];
    const float* conv_b = (const float*)d_in[4];
    float* out = (float*)d_out;

    prep_weights<<<dim3(96, 4, 16), dim3(32, 8)>>>(kern, conv_w);

    int smem_bytes = SMEM_U32 * 4;   // 52,640 B
    cudaFuncSetAttribute(lvc_mma_kernel,
                         cudaFuncAttributeMaxDynamicSharedMemorySize, smem_bytes);
    lvc_mma_kernel<<<dim3(KLCH, BATCH), 256, smem_bytes>>>(hidden, bias, conv_w, conv_b, out);
}

// round 15
// speedup vs baseline: 2.4639x; 1.0187x over previous
#include <cuda_runtime.h>
#include <cuda_fp16.h>
#include <stdint.h>

#define HID   32
#define LEN   32768
#define BATCH 16
#define KLCH  128

#define HSS 136     // hs row stride (fp32 words)
#define TS  20      // hT/xT row stride in u32 (40 half)

// smem u32 offsets
#define OF_W2   0       // 3072 : LVC W, per-shift frag order (half2)
#define OF_BIAS 3072    // 64 (fp32)
#define OF_CB   3136    // 32 (fp32)
#define OF_HS   3168    // 4352 : raw fp32 hidden tile (single buffer)
#define OF_HT   7520    // 3040 : hT[152][40 half]; rows 136..151 zero
#define OF_XT   10560   // 2600 : xT[130][40 half]
#define SMEM_U32 13160  // 52,640 B -> 4 CTA/SM (register-capped too)

// weights pre-packed per-shift (k=0..2), K=32, m16n8k16 B-frag order, half2-in-u32
__device__ __align__(16) uint32_t g_kth[(size_t)BATCH * KLCH * 3072];  // 25 MB
__device__ __align__(16) uint32_t g_w1h[1536];

__device__ __forceinline__ float fast_tanh(float x) { float r; asm("tanh.approx.f32 %0, %1;" : "=f"(r) : "f"(x)); return r; }
__device__ __forceinline__ float fast_ex2(float x)  { float r; asm("ex2.approx.f32 %0, %1;"  : "=f"(r) : "f"(x)); return r; }
__device__ __forceinline__ float fast_rcp(float x)  { float r; asm("rcp.approx.f32 %0, %1;"  : "=f"(r) : "f"(x)); return r; }
__device__ __forceinline__ float leaky(float x) { return (x >= 0.f) ? x : 0.2f * x; }

__device__ __forceinline__ uint32_t smem_u32p(const void* p) {
    uint32_t a; asm("{ .reg .u64 t; cvta.to.shared.u64 t, %1; cvt.u32.u64 %0, t; }" : "=r"(a) : "l"(p));
    return a;
}
__device__ __forceinline__ void cp_async16(uint32_t dst, const void* src, int src_bytes) {
    asm volatile("cp.async.ca.shared.global [%0], [%1], 16, %2;"
                 :: "r"(dst), "l"(src), "r"(src_bytes) : "memory");
}
__device__ __forceinline__ void mma_fp16(float c[4],
                                         uint32_t a0, uint32_t a1, uint32_t a2, uint32_t a3,
                                         uint32_t b0, uint32_t b1) {
    asm volatile(
        "mma.sync.aligned.m16n8k16.row.col.f32.f16.f16.f32 "
        "{%0,%1,%2,%3}, {%4,%5,%6,%7}, {%8,%9}, {%0,%1,%2,%3};"
        : "+f"(c[0]), "+f"(c[1]), "+f"(c[2]), "+f"(c[3])
        : "r"(a0), "r"(a1), "r"(a2), "r"(a3), "r"(b0), "r"(b1));
}
__device__ __forceinline__ void ldsm4(uint32_t* a, uint32_t addr) {
    asm volatile("ldmatrix.sync.aligned.m8n8.x4.shared.b16 {%0,%1,%2,%3}, [%4];"
                 : "=r"(a[0]), "=r"(a[1]), "=r"(a[2]), "=r"(a[3]) : "r"(addr));
}
__device__ __forceinline__ uint32_t packh2(float lo, float hi) {
    __half2 h = __floats2half2_rn(lo, hi);
    return *reinterpret_cast<uint32_t*>(&h);
}

// ---------------------------------------------------------------------------
// Prep: kernel[b,i,o,k,l] -> g_kth[b][l][k*1024 + f2]  (per-shift B-frag order)
// Also (block 0,0,0) packs conv_w -> g_w1h[k*512 + f1].
// ---------------------------------------------------------------------------
__global__ void prep_weights(const float* __restrict__ kin,
                             const float* __restrict__ conv_w) {
    __shared__ uint32_t tile[32][33];
    int b  = blockIdx.z;
    int f0 = blockIdx.x * 32;
    int l0 = blockIdx.y * 32;
    int tx = threadIdx.x, ty = threadIdx.y;
    const float* src = kin + (size_t)b * 6144 * 128;
    uint32_t*    dst = g_kth + (size_t)b * 128 * 3072;
#pragma unroll
    for (int r = 0; r < 4; r++) {
        int f = f0 + ty + r * 8;
        int k = f >> 10, f2 = f & 1023;
        int j = f2 & 3, lane = (f2 >> 2) & 31, blk = f2 >> 7;  // blk = ks*4+q
        int q = blk & 3, ks = blk >> 2;
        int tq = lane & 3, tr = lane >> 2;
        int nt = 2 * q + (j >> 1), reg = j & 1;
        int o  = nt * 8 + tr;
        int ci0 = ks * 16 + 2 * tq + 8 * reg;
        int mlo = ci0 * 192 + o * 3 + k;
        int mhi = (ci0 + 1) * 192 + o * 3 + k;
        tile[ty + r * 8][tx] = packh2(src[(size_t)mlo * 128 + l0 + tx],
                                      src[(size_t)mhi * 128 + l0 + tx]);
    }
    __syncthreads();
#pragma unroll
    for (int r = 0; r < 4; r++) {
        int l = l0 + ty + r * 8;
        dst[(size_t)l * 3072 + f0 + tx] = tile[tx][ty + r * 8];
    }
    if (blockIdx.x == 0 && blockIdx.y == 0 && blockIdx.z == 0) {
        int t = ty * 32 + tx;
        for (int f = t; f < 1536; f += 256) {
            int k = f >> 9, f1 = f & 511;
            int j = f1 & 3, lane = (f1 >> 2) & 31, blk = f1 >> 7;  // blk = ks*2+q
            int q = blk & 1, ks = blk >> 1;
            int tq = lane & 3, tr = lane >> 2;
            int nt = 2 * q + (j >> 1), reg = j & 1;
            int co = nt * 8 + tr;
            int ci0 = ks * 16 + 2 * tq + 8 * reg;
            g_w1h[f] = packh2(conv_w[co * 96 + 3 * ci0 + k],
                              conv_w[co * 96 + 3 * (ci0 + 1) + k]);
        }
    }
}

// ---------------------------------------------------------------------------
// Main fused kernel: one CTA per (256-position chunk, batch); 2 pipelined subs.
// ---------------------------------------------------------------------------
__global__ __launch_bounds__(256, 4)
void lvc_mma_kernel(const float* __restrict__ hidden,
                    const float* __restrict__ bias,
                    const float* __restrict__ conv_w,
                    const float* __restrict__ conv_b,
                    float* __restrict__ out) {
    extern __shared__ float sm[];
    uint32_t* w2u   = (uint32_t*)(sm + OF_W2);
    float*    biasS = sm + OF_BIAS;
    float*    cbS   = sm + OF_CB;
    float*    hsf   = sm + OF_HS;
    uint32_t* hTu   = (uint32_t*)(sm + OF_HT);
    uint32_t* xTu   = (uint32_t*)(sm + OF_XT);
    const __half* hTh = (const __half*)hTu;

    const int tid  = threadIdx.x;
    const int wid  = tid >> 5;
    const int lane = tid & 31;
    const int l    = blockIdx.x;
    const int b    = blockIdx.y;
    const float* hidB = hidden + (size_t)b * HID * LEN;
    const uint32_t hb = smem_u32p(hsf);
    const uint32_t w2b = smem_u32p(w2u);

    // ---- group 0: prefetch sub0's hs tile (raw fp32) ----
    {
        const int s0p = l * 256;
        for (int idx = tid; idx < 1088; idx += 256) {
            int c = idx / 34, gr = idx - c * 34;
            int g = s0p - 4 + gr * 4;
            bool in = (g >= 0) && (g + 4 <= LEN);
            const float* src = hidB + (size_t)c * LEN + (in ? g : 0);
            cp_async16(hb + (uint32_t)(c * HSS + gr * 4) * 4, src, in ? 16 : 0);
        }
        asm volatile("cp.async.commit_group;" ::: "memory");
    }
    // ---- group 1: stage w2 via cp.async (overlaps P1 + stage-1) ----
    {
        const uint4* w2s = (const uint4*)(g_kth + ((size_t)b * KLCH + l) * 3072);
        for (int i = tid; i < 768; i += 256)
            cp_async16(w2b + (uint32_t)i * 16, w2s + i, 16);
        asm volatile("cp.async.commit_group;" ::: "memory");
        for (int i = tid; i < 320; i += 256) hTu[2720 + i] = 0;   // hT pad rows
    }
    if (tid < 64) biasS[tid] = bias[((size_t)b * 64 + tid) * KLCH + l];
    if (tid < 32) cbS[tid]   = conv_b[tid];

    const int tq = lane & 3;
    const int tr = lane >> 2;
    const int m0 = wid * 16;          // stage-1 m-tile
    const int mt2 = wid & 3;          // stage-2: 32-row block
    const int nh  = wid >> 2;         // stage-2: n-half (q parity)

    // P1 diagonal transpose mapping (conflict-free loads AND stores)
    const int ceP = tid & 15;
    const int g2P = tid >> 4;

    // ldmatrix lane base addresses (row = lane&15, col-u32 = (lane>>4)*4)
    const uint32_t hT_lane = smem_u32p(hTu) + (uint32_t)(((lane & 15) * TS + (lane >> 4) * 4) * 4);
    const uint32_t xT_lane = smem_u32p(xTu) + (uint32_t)(((lane & 15) * TS + (lane >> 4) * 4) * 4);

    const uint4* w1g = (const uint4*)g_w1h;   // stage-1 B from global (L1-resident)

#pragma unroll
    for (int s = 0; s < 2; s++) {
        const int s0 = l * 256 + s * 128;

        // s==0: need hs(g0); w2(g1) may still be in flight. s==1: need all.
        if (s == 0) asm volatile("cp.async.wait_group 1;" ::: "memory");
        else        asm volatile("cp.async.wait_group 0;" ::: "memory");
        __syncthreads();

        // ---- P1: build hT — diagonal float2 transpose, conflict-free ----
#pragma unroll
        for (int it = 0; it < 5; it++) {
            int vp = it * 16 + g2P + ceP;
            if (vp >= 80) vp -= 80;
            if (vp < 68) {
                float2 lo2 = *(const float2*)(hsf + (2 * ceP)     * HSS + 2 * vp);
                float2 hi2 = *(const float2*)(hsf + (2 * ceP + 1) * HSS + 2 * vp);
                hTu[(2 * vp)     * TS + ceP] = packh2(leaky(lo2.x), leaky(hi2.x));
                hTu[(2 * vp + 1) * TS + ceP] = packh2(leaky(lo2.y), leaky(hi2.y));
            }
        }
        __syncthreads();   // hT complete AND hs reads complete

        // hs is dead: group 2 = prefetch next sub's tile into the same buffer
        if (s == 0) {
            const int s0p = l * 256 + 128;
            for (int idx = tid; idx < 1088; idx += 256) {
                int c = idx / 34, gr = idx - c * 34;
                int g = s0p - 4 + gr * 4;
                bool in = (g >= 0) && (g + 4 <= LEN);
                const float* src = hidB + (size_t)c * LEN + (in ? g : 0);
                cp_async16(hb + (uint32_t)(c * HSS + gr * 4) * 4, src, in ? 16 : 0);
            }
            asm volatile("cp.async.commit_group;" ::: "memory");
        }

        // ---- P2: stage-1 shift-GEMM: 16m x 32n per warp, ldmatrix A ----
        float c1[4][4];
#pragma unroll
        for (int nt = 0; nt < 4; nt++)
#pragma unroll
            for (int j = 0; j < 4; j++) c1[nt][j] = 0.f;

#pragma unroll
        for (int k = 0; k < 3; k++) {
#pragma unroll
            for (int ks = 0; ks < 2; ks++) {
                uint32_t A[4];
                ldsm4(A, hT_lane + (uint32_t)(((m0 + 3 * k) * TS + ks * 8) * 4));
                uint4 q0 = w1g[k * 128 + ks * 64 + lane];
                uint4 q1 = w1g[k * 128 + ks * 64 + 32 + lane];
                mma_fp16(c1[0], A[0], A[1], A[2], A[3], q0.x, q0.y);
                mma_fp16(c1[1], A[0], A[1], A[2], A[3], q0.z, q0.w);
                mma_fp16(c1[2], A[0], A[1], A[2], A[3], q1.x, q1.y);
                mma_fp16(c1[3], A[0], A[1], A[2], A[3], q1.z, q1.w);
            }
        }

        // ---- P3: write xT — paired u32 stores, conflict-free ----
        {
            const int u = m0 + tr;
            const bool z0 = (s0 == 0) && (u == 0);
#pragma unroll
            for (int nt = 0; nt < 4; nt++) {
                int c  = nt * 8 + 2 * tq;
                int cw = nt * 4 + tq;
                float bA = cbS[c], bB = cbS[c + 1];
                uint32_t wlo = packh2(leaky(c1[nt][0] + bA), leaky(c1[nt][1] + bB));
                uint32_t whi = packh2(leaky(c1[nt][2] + bA), leaky(c1[nt][3] + bB));
                xTu[u * TS + cw]       = z0 ? 0u : wlo;
                xTu[(u + 8) * TS + cw] = whi;
            }
        }
        // tail rows u = 128,129 via an extra MMA tile on warp 0
        if (wid == 0) {
            float c1b[4][4];
#pragma unroll
            for (int nt = 0; nt < 4; nt++)
#pragma unroll
                for (int j = 0; j < 4; j++) c1b[nt][j] = 0.f;
#pragma unroll
            for (int k = 0; k < 3; k++) {
#pragma unroll
                for (int ks = 0; ks < 2; ks++) {
                    uint32_t A[4];
                    ldsm4(A, hT_lane + (uint32_t)(((128 + 3 * k) * TS + ks * 8) * 4));
                    uint4 q0 = w1g[k * 128 + ks * 64 + lane];
                    uint4 q1 = w1g[k * 128 + ks * 64 + 32 + lane];
                    mma_fp16(c1b[0], A[0], A[1], A[2], A[3], q0.x, q0.y);
                    mma_fp16(c1b[1], A[0], A[1], A[2], A[3], q0.z, q0.w);
                    mma_fp16(c1b[2], A[0], A[1], A[2], A[3], q1.x, q1.y);
                    mma_fp16(c1b[3], A[0], A[1], A[2], A[3], q1.z, q1.w);
                }
            }
            if (tr < 2) {
                int u = 128 + tr;               // p = s0 + 127 + tr
                bool ok = (s0 + 127 + tr) < LEN;
#pragma unroll
                for (int nt = 0; nt < 4; nt++) {
                    int c  = nt * 8 + 2 * tq;
                    uint32_t w = packh2(leaky(c1b[nt][0] + cbS[c]),
                                        leaky(c1b[nt][1] + cbS[c + 1]));
                    xTu[u * TS + nt * 4 + tq] = ok ? w : 0u;
                }
            }
        }
        // first sub: make sure w2 (group 1) has landed before stage-2 reads it
        if (s == 0) asm volatile("cp.async.wait_group 1;" ::: "memory");
        __syncthreads();

        // ---- P4: stage-2 shift-GEMM: 32m x 32n per warp (q-parity n-split) ----
        // Batched loads first (MLP=4), then 16 MMAs.
        float c2[2][4][4];
#pragma unroll
        for (int mt = 0; mt < 2; mt++)
#pragma unroll
            for (int ni = 0; ni < 4; ni++)
#pragma unroll
                for (int j = 0; j < 4; j++) c2[mt][ni][j] = 0.f;

        const uint4* w2q = (const uint4*)w2u;
#pragma unroll
        for (int k = 0; k < 3; k++) {
#pragma unroll
            for (int ks = 0; ks < 2; ks++) {
                uint32_t A0[4], A1[4];
                ldsm4(A0, xT_lane + (uint32_t)(((mt2 * 32 + k) * TS + ks * 8) * 4));
                ldsm4(A1, xT_lane + (uint32_t)(((mt2 * 32 + 16 + k) * TS + ks * 8) * 4));
                uint4 qa = w2q[k * 256 + ks * 128 + nh * 32 + lane];        // nt 2nh, 2nh+1
                uint4 qb = w2q[k * 256 + ks * 128 + (nh + 2) * 32 + lane];  // nt 2nh+4, 2nh+5
                mma_fp16(c2[0][0], A0[0], A0[1], A0[2], A0[3], qa.x, qa.y);
                mma_fp16(c2[0][1], A0[0], A0[1], A0[2], A0[3], qa.z, qa.w);
                mma_fp16(c2[0][2], A0[0], A0[1], A0[2], A0[3], qb.x, qb.y);
                mma_fp16(c2[0][3], A0[0], A0[1], A0[2], A0[3], qb.z, qb.w);
                mma_fp16(c2[1][0], A1[0], A1[1], A1[2], A1[3], qa.x, qa.y);
                mma_fp16(c2[1][1], A1[0], A1[1], A1[2], A1[3], qa.z, qa.w);
                mma_fp16(c2[1][2], A1[0], A1[1], A1[2], A1[3], qb.x, qb.y);
                mma_fp16(c2[1][3], A1[0], A1[1], A1[2], A1[3], qb.z, qb.w);
            }
        }

        // ---- epilogue: gate + residual (residual = inverse-leaky of hT) ----
        {
            float* outB = out + (size_t)b * HID * LEN;
            const float LOG2E = 1.4426950408889634f;
#pragma unroll
            for (int mt = 0; mt < 2; mt++) {
#pragma unroll
                for (int ni = 0; ni < 2; ni++) {
                    int obase = (2 * nh + ni) * 8 + 2 * tq;
#pragma unroll
                    for (int j = 0; j < 4; j++) {
                        int oo = obase + (j & 1);
                        int m  = mt2 * 32 + mt * 16 + tr + ((j >> 1) << 3);
                        float gv = c2[mt][ni][j]     + biasS[oo];
                        float hv = c2[mt][ni + 2][j] + biasS[oo + 32];
                        float sig = fast_rcp(1.f + fast_ex2(-LOG2E * gv));
                        float ry = __half2float(hTh[(m + 4) * 40 + oo]);
                        float res = (ry >= 0.f) ? ry : 5.f * ry;
                        outB[(size_t)oo * LEN + s0 + m] = res + sig * fast_tanh(hv);
                    }
                }
            }
        }
    }
}

// ---------------------------------------------------------------------------
extern "C" void kernel_launch(void* const* d_in, const int* in_sizes, int n_in,
                              void* d_out, int out_size) {
    const float* hidden = (const float*)d_in[0];
    const float* kern   = (const float*)d_in[1];
    const float* bias   = (const float*)d_in[2];
    const float* conv_w = (const float*)d_in[3];
    const float* conv_b = (const float*)d_in[4];
    float* out = (float*)d_out;

    prep_weights<<<dim3(96, 4, 16), dim3(32, 8)>>>(kern, conv_w);

    int smem_bytes = SMEM_U32 * 4;   // 52,640 B
    cudaFuncSetAttribute(lvc_mma_kernel,
                         cudaFuncAttributeMaxDynamicSharedMemorySize, smem_bytes);
    lvc_mma_kernel<<<dim3(KLCH, BATCH), 256, smem_bytes>>>(hidden, bias, conv_w, conv_b, out);
}